// round 1
// baseline (speedup 1.0000x reference)
#include <cuda_runtime.h>
#include <math.h>

#define Bn 4
#define Sn 2048
#define En 1024
#define Hn 16
#define HDn 64
#define Tn (Bn*Sn)        // 8192 tokens
#define F1n (3*En)        // 3072

// Scratch (static device globals — allocation-free per harness rules)
__device__ float g_q[(size_t)Bn*Hn*Sn*HDn];   // [b*H+h][s][d]
__device__ float g_k[(size_t)Bn*Hn*Sn*HDn];
__device__ float g_v[(size_t)Bn*Hn*Sn*HDn];
__device__ float g_att[(size_t)Tn*En];        // [t][e]

// ---------------------------------------------------------------------------
// Kernel 1: QKV GEMM.  C[t][f] = sum_e x[t][e] * w_qkv[f][e]
// 128x128 block tile, BK=16, 256 threads, 8x8 per thread.
// Scatter result into head-major Q/K/V per reference's view(B,S,H,3*HD) split.
// ---------------------------------------------------------------------------
__global__ __launch_bounds__(256) void qkv_gemm_kernel(
    const float* __restrict__ x, const float* __restrict__ w)
{
    __shared__ float As[16][132];
    __shared__ float Bs[16][132];
    const int tid = threadIdx.x;
    const int tx = tid & 15, ty = tid >> 4;
    const int t0 = blockIdx.y * 128, f0 = blockIdx.x * 128;
    const int lr = tid >> 2;          // 0..63
    const int lc = (tid & 3) << 2;    // 0,4,8,12

    float acc[8][8] = {};

    for (int k0 = 0; k0 < En; k0 += 16) {
        #pragma unroll
        for (int r = 0; r < 2; r++) {
            float4 a = *(const float4*)(x + (size_t)(t0 + lr + r*64) * En + k0 + lc);
            As[lc+0][lr+r*64]=a.x; As[lc+1][lr+r*64]=a.y;
            As[lc+2][lr+r*64]=a.z; As[lc+3][lr+r*64]=a.w;
            float4 b = *(const float4*)(w + (size_t)(f0 + lr + r*64) * En + k0 + lc);
            Bs[lc+0][lr+r*64]=b.x; Bs[lc+1][lr+r*64]=b.y;
            Bs[lc+2][lr+r*64]=b.z; Bs[lc+3][lr+r*64]=b.w;
        }
        __syncthreads();
        #pragma unroll
        for (int k = 0; k < 16; k++) {
            float a[8], b[8];
            *(float4*)(a)   = *(const float4*)&As[k][ty*8];
            *(float4*)(a+4) = *(const float4*)&As[k][ty*8+4];
            *(float4*)(b)   = *(const float4*)&Bs[k][tx*8];
            *(float4*)(b+4) = *(const float4*)&Bs[k][tx*8+4];
            #pragma unroll
            for (int i = 0; i < 8; i++)
                #pragma unroll
                for (int j = 0; j < 8; j++)
                    acc[i][j] = fmaf(a[i], b[j], acc[i][j]);
        }
        __syncthreads();
    }

    #pragma unroll
    for (int i = 0; i < 8; i++) {
        int t = t0 + ty*8 + i;
        int b = t >> 11, s = t & 2047;
        #pragma unroll
        for (int j = 0; j < 8; j++) {
            int f = f0 + tx*8 + j;
            int h = f / 192;
            int c = f - h * 192;
            int kind = c >> 6, d = c & 63;
            float* dst = (kind == 0) ? g_q : ((kind == 1) ? g_k : g_v);
            dst[(((size_t)(b*Hn + h))*Sn + s)*HDn + d] = acc[i][j];
        }
    }
}

// ---------------------------------------------------------------------------
// Kernel 2: causal flash attention, fp32, 64x64 tiles, online softmax.
// grid = (32 q-tiles, 64 batch*heads), 256 threads, 4x4 per thread.
// ---------------------------------------------------------------------------
__global__ __launch_bounds__(256) void attn_kernel()
{
    extern __shared__ float sm[];
    float* Qt = sm;               // [64][64]  d-major (transposed)
    float* Kt = sm + 4096;        // [64][64]  d-major (transposed)
    float* Vs = sm + 8192;        // [64][64]  n-major
    float* Ss = sm + 12288;       // [64][65]  padded
    float* rm = Ss + 64*65;       // row max
    float* rl = rm + 64;          // row sum
    float* ra = rl + 64;          // row alpha

    const int tid = threadIdx.x;
    const int tx = tid & 15, ty = tid >> 4;
    const int bh = blockIdx.y;    // b*H + h
    const int qt = blockIdx.x;
    const size_t base = (size_t)bh * Sn * HDn;
    const float* Q = g_q + base;
    const float* K = g_k + base;
    const float* V = g_v + base;

    const int lr = tid >> 2;          // 0..63 (row within tile)
    const int lc = (tid & 3) * 16;    // 0,16,32,48

    // Load Q tile transposed (once)
    {
        const float* qrow = Q + (size_t)(qt*64 + lr)*HDn + lc;
        #pragma unroll
        for (int i = 0; i < 4; i++) {
            float4 v4 = *(const float4*)(qrow + i*4);
            Qt[(lc+i*4+0)*64 + lr] = v4.x;
            Qt[(lc+i*4+1)*64 + lr] = v4.y;
            Qt[(lc+i*4+2)*64 + lr] = v4.z;
            Qt[(lc+i*4+3)*64 + lr] = v4.w;
        }
    }
    if (tid < 64) { rm[tid] = -INFINITY; rl[tid] = 0.f; }

    float acc_o[4][4] = {};

    for (int kt = 0; kt <= qt; kt++) {
        __syncthreads();   // protect Kt/Vs/Ss from previous iteration's readers
        // Load K transposed, V direct
        {
            const float* krow = K + (size_t)(kt*64 + lr)*HDn + lc;
            #pragma unroll
            for (int i = 0; i < 4; i++) {
                float4 v4 = *(const float4*)(krow + i*4);
                Kt[(lc+i*4+0)*64 + lr] = v4.x;
                Kt[(lc+i*4+1)*64 + lr] = v4.y;
                Kt[(lc+i*4+2)*64 + lr] = v4.z;
                Kt[(lc+i*4+3)*64 + lr] = v4.w;
            }
            const float* vrow = V + (size_t)(kt*64 + lr)*HDn + lc;
            #pragma unroll
            for (int i = 0; i < 4; i++)
                *(float4*)(Vs + lr*64 + lc + i*4) = *(const float4*)(vrow + i*4);
        }
        __syncthreads();

        // S = Q @ K^T  (4x4 per thread)
        float acc_s[4][4] = {};
        #pragma unroll 8
        for (int d = 0; d < 64; d++) {
            float4 a4 = *(const float4*)(Qt + d*64 + ty*4);
            float4 b4 = *(const float4*)(Kt + d*64 + tx*4);
            float a[4] = {a4.x, a4.y, a4.z, a4.w};
            float b[4] = {b4.x, b4.y, b4.z, b4.w};
            #pragma unroll
            for (int i = 0; i < 4; i++)
                #pragma unroll
                for (int j = 0; j < 4; j++)
                    acc_s[i][j] = fmaf(a[i], b[j], acc_s[i][j]);
        }
        // scale + causal mask + store to smem
        #pragma unroll
        for (int i = 0; i < 4; i++) {
            int qi = qt*64 + ty*4 + i;
            #pragma unroll
            for (int j = 0; j < 4; j++) {
                int ki = kt*64 + tx*4 + j;
                float v = acc_s[i][j] * 0.125f;      // HD^-0.5
                Ss[(ty*4+i)*65 + tx*4 + j] = (ki > qi) ? -INFINITY : v;
            }
        }
        __syncthreads();

        // Online softmax: one thread per row (rows 0..63), stride-65 = conflict-free
        if (tid < 64) {
            int r = tid;
            float mold = rm[r];
            float mx = mold;
            #pragma unroll 8
            for (int n = 0; n < 64; n++) mx = fmaxf(mx, Ss[r*65+n]);
            float alpha = expf(mold - mx);
            float sum = 0.f;
            #pragma unroll 8
            for (int n = 0; n < 64; n++) {
                float p = expf(Ss[r*65+n] - mx);
                Ss[r*65+n] = p;
                sum += p;
            }
            rm[r] = mx;
            rl[r] = rl[r]*alpha + sum;
            ra[r] = alpha;
        }
        __syncthreads();

        // Rescale accumulators, then O += P @ V
        #pragma unroll
        for (int i = 0; i < 4; i++) {
            float al = ra[ty*4+i];
            #pragma unroll
            for (int j = 0; j < 4; j++) acc_o[i][j] *= al;
        }
        #pragma unroll 4
        for (int n = 0; n < 64; n++) {
            float4 v4 = *(const float4*)(Vs + n*64 + tx*4);
            float vv[4] = {v4.x, v4.y, v4.z, v4.w};
            float p[4];
            #pragma unroll
            for (int i = 0; i < 4; i++) p[i] = Ss[(ty*4+i)*65 + n];
            #pragma unroll
            for (int i = 0; i < 4; i++)
                #pragma unroll
                for (int j = 0; j < 4; j++)
                    acc_o[i][j] = fmaf(p[i], vv[j], acc_o[i][j]);
        }
    }

    // Normalize and write to g_att[t][e], e = h*64 + d
    const int b = bh >> 4, h = bh & 15;
    #pragma unroll
    for (int i = 0; i < 4; i++) {
        int m = ty*4 + i;
        float inv = 1.f / rl[m];
        int t = b*Sn + qt*64 + m;
        #pragma unroll
        for (int j = 0; j < 4; j++)
            g_att[(size_t)t*En + h*64 + tx*4 + j] = acc_o[i][j] * inv;
    }
}

// ---------------------------------------------------------------------------
// Kernel 3: output projection GEMM + bias.
// out[t][f] = sum_e g_att[t][e] * w_proj[f][e] + b_proj[f]
// ---------------------------------------------------------------------------
__global__ __launch_bounds__(256) void proj_gemm_kernel(
    const float* __restrict__ w, const float* __restrict__ bias,
    float* __restrict__ out)
{
    __shared__ float As[16][132];
    __shared__ float Bs[16][132];
    const int tid = threadIdx.x;
    const int tx = tid & 15, ty = tid >> 4;
    const int t0 = blockIdx.y * 128, f0 = blockIdx.x * 128;
    const int lr = tid >> 2;
    const int lc = (tid & 3) << 2;

    float acc[8][8] = {};

    for (int k0 = 0; k0 < En; k0 += 16) {
        #pragma unroll
        for (int r = 0; r < 2; r++) {
            float4 a = *(const float4*)(g_att + (size_t)(t0 + lr + r*64) * En + k0 + lc);
            As[lc+0][lr+r*64]=a.x; As[lc+1][lr+r*64]=a.y;
            As[lc+2][lr+r*64]=a.z; As[lc+3][lr+r*64]=a.w;
            float4 b = *(const float4*)(w + (size_t)(f0 + lr + r*64) * En + k0 + lc);
            Bs[lc+0][lr+r*64]=b.x; Bs[lc+1][lr+r*64]=b.y;
            Bs[lc+2][lr+r*64]=b.z; Bs[lc+3][lr+r*64]=b.w;
        }
        __syncthreads();
        #pragma unroll
        for (int k = 0; k < 16; k++) {
            float a[8], b[8];
            *(float4*)(a)   = *(const float4*)&As[k][ty*8];
            *(float4*)(a+4) = *(const float4*)&As[k][ty*8+4];
            *(float4*)(b)   = *(const float4*)&Bs[k][tx*8];
            *(float4*)(b+4) = *(const float4*)&Bs[k][tx*8+4];
            #pragma unroll
            for (int i = 0; i < 8; i++)
                #pragma unroll
                for (int j = 0; j < 8; j++)
                    acc[i][j] = fmaf(a[i], b[j], acc[i][j]);
        }
        __syncthreads();
    }

    #pragma unroll
    for (int i = 0; i < 8; i++) {
        int t = t0 + ty*8 + i;
        #pragma unroll
        for (int j = 0; j < 8; j++) {
            int f = f0 + tx*8 + j;
            out[(size_t)t*En + f] = acc[i][j] + bias[f];
        }
    }
}

// ---------------------------------------------------------------------------
extern "C" void kernel_launch(void* const* d_in, const int* in_sizes, int n_in,
                              void* d_out, int out_size)
{
    const float* x      = (const float*)d_in[0];
    const float* w_qkv  = (const float*)d_in[1];
    const float* w_proj = (const float*)d_in[2];
    const float* b_proj = (const float*)d_in[3];
    float* out = (float*)d_out;

    cudaFuncSetAttribute(attn_kernel,
                         cudaFuncAttributeMaxDynamicSharedMemorySize, 66560);

    qkv_gemm_kernel<<<dim3(F1n/128, Tn/128), 256>>>(x, w_qkv);   // (24, 64)
    attn_kernel<<<dim3(Sn/64, Bn*Hn), 256, 66560>>>();           // (32, 64)
    proj_gemm_kernel<<<dim3(En/128, Tn/128), 256>>>(w_proj, b_proj, out); // (8, 64)
}

// round 3
// speedup vs baseline: 1.3761x; 1.3761x over previous
#include <cuda_runtime.h>
#include <cuda_bf16.h>
#include <math.h>
#include <stdint.h>

#define Bn 4
#define Sn 2048
#define En 1024
#define Hn 16
#define HDn 64
#define Tn (Bn*Sn)        // 8192 tokens
#define F1n (3*En)        // 3072

// ---------------------------------------------------------------------------
// Scratch (static device globals — allocation-free per harness rules)
// ---------------------------------------------------------------------------
__device__ float g_q[(size_t)Bn*Hn*Sn*HDn];   // [b*H+h][s][d]
__device__ float g_k[(size_t)Bn*Hn*Sn*HDn];
__device__ float g_v[(size_t)Bn*Hn*Sn*HDn];
__device__ __nv_bfloat16 g_x_hi[(size_t)Tn*En];
__device__ __nv_bfloat16 g_x_lo[(size_t)Tn*En];
__device__ __nv_bfloat16 g_wq_hi[(size_t)F1n*En];
__device__ __nv_bfloat16 g_wq_lo[(size_t)F1n*En];
__device__ __nv_bfloat16 g_wp_hi[(size_t)En*En];
__device__ __nv_bfloat16 g_wp_lo[(size_t)En*En];
__device__ __nv_bfloat16 g_att_hi[(size_t)Tn*En];
__device__ __nv_bfloat16 g_att_lo[(size_t)Tn*En];

// ---------------------------------------------------------------------------
// Helpers (baseline PTX only — no 'a'-suffix arch features)
// ---------------------------------------------------------------------------
__device__ __forceinline__ uint32_t smem_u32(const void* p) {
    uint32_t a;
    asm("{ .reg .u64 t; cvta.to.shared.u64 t, %1; cvt.u32.u64 %0, t; }" : "=r"(a) : "l"(p));
    return a;
}

__device__ __forceinline__ void ldgsts16(uint32_t dst, const void* src) {
    asm volatile("cp.async.cg.shared.global [%0], [%1], 16;" :: "r"(dst), "l"(src));
}

#define LDSM_X4(r0, r1, r2, r3, addr) \
    asm volatile("ldmatrix.sync.aligned.m8n8.x4.shared.b16 {%0,%1,%2,%3}, [%4];" \
        : "=r"(r0), "=r"(r1), "=r"(r2), "=r"(r3) : "r"(addr))

__device__ __forceinline__ void mma16816(float c[4], const uint32_t a[4],
                                         uint32_t b0, uint32_t b1) {
    asm volatile(
        "mma.sync.aligned.m16n8k16.row.col.f32.bf16.bf16.f32 "
        "{%0,%1,%2,%3}, {%4,%5,%6,%7}, {%8,%9}, {%0,%1,%2,%3};"
        : "+f"(c[0]), "+f"(c[1]), "+f"(c[2]), "+f"(c[3])
        : "r"(a[0]), "r"(a[1]), "r"(a[2]), "r"(a[3]), "r"(b0), "r"(b1));
}

// ---------------------------------------------------------------------------
// Kernel 0: fp32 -> (bf16 hi, bf16 lo) split, float4-vectorized
// ---------------------------------------------------------------------------
__global__ __launch_bounds__(256) void split_kernel(
    const float4* __restrict__ src, __nv_bfloat162* __restrict__ hi,
    __nv_bfloat162* __restrict__ lo, int n4)
{
    int i = blockIdx.x * 256 + threadIdx.x;
    if (i >= n4) return;
    float4 v = src[i];
    __nv_bfloat16 h0 = __float2bfloat16(v.x), h1 = __float2bfloat16(v.y);
    __nv_bfloat16 h2 = __float2bfloat16(v.z), h3 = __float2bfloat16(v.w);
    __nv_bfloat16 l0 = __float2bfloat16(v.x - __bfloat162float(h0));
    __nv_bfloat16 l1 = __float2bfloat16(v.y - __bfloat162float(h1));
    __nv_bfloat16 l2 = __float2bfloat16(v.z - __bfloat162float(h2));
    __nv_bfloat16 l3 = __float2bfloat16(v.w - __bfloat162float(h3));
    __nv_bfloat162 a; a.x = h0; a.y = h1;
    __nv_bfloat162 b; b.x = h2; b.y = h3;
    __nv_bfloat162 c; c.x = l0; c.y = l1;
    __nv_bfloat162 d; d.x = l2; d.y = l3;
    hi[2*i] = a; hi[2*i+1] = b;
    lo[2*i] = c; lo[2*i+1] = d;
}

// ---------------------------------------------------------------------------
// Split-bf16 HMMA GEMM.  C[r][f] = sum_k A[r][k]*B[f][k]   (K = 1024)
// BM=128, BN=256, BK=32. 8 warps, each computes a 64x64 tile (2x4 warp grid).
// D = Ahi*Bhi + Ahi*Blo + Alo*Bhi  (fp32 accum; lo*lo dropped, ~2^-16 rel)
// Smem rows padded to 80B (40 bf16): row*20 words mod 32 distinct => ldmatrix
// conflict-free. 2-stage cp.async double buffer.
//   mode 0: scatter C (fp32) into head-major g_q/g_k/g_v
//   mode 1: C + bias -> out (fp32, row-major)
// ---------------------------------------------------------------------------
#define BMm 128
#define BNn 256
#define BKk 32
#define NKI (En/BKk)            // 32
#define ROWB 80                 // padded row stride in bytes (32 bf16 + 8 pad)
#define OFF_ALO 10240           // 128*80
#define OFF_BHI 20480
#define OFF_BLO 40960           // 20480 + 256*80
#define STAGEB  61440           // 40960 + 256*80
#define GEMM_SMEM (2*STAGEB)    // 122880

__global__ __launch_bounds__(256) void gemm_split_kernel(
    const __nv_bfloat16* __restrict__ Ahi, const __nv_bfloat16* __restrict__ Alo,
    const __nv_bfloat16* __restrict__ Bhi, const __nv_bfloat16* __restrict__ Blo,
    float* __restrict__ outp, const float* __restrict__ bias, int mode)
{
    extern __shared__ char dsm[];
    const uint32_t sb = smem_u32(dsm);
    const int tid = threadIdx.x;
    const int wid = tid >> 5, lane = tid & 31;
    const int wy = wid & 1, wx = wid >> 1;          // warp tile: (wy*64, wx*64)
    const int t0 = blockIdx.y * BMm, f0 = blockIdx.x * BNn;

    // --------- stage loader (48KB data; 12 x 16B cp.async per thread) -------
    #define LOAD_STAGE(ki, s) do {                                            \
        uint32_t base_ = sb + (uint32_t)(s)*STAGEB;                           \
        int kofs_ = (ki)*BKk;                                                 \
        _Pragma("unroll")                                                     \
        for (int jj = 0; jj < 2; jj++) {                                      \
            int c_ = tid + jj*256;                                            \
            int row_ = c_ >> 2, ch_ = c_ & 3;                                 \
            uint32_t so_ = (uint32_t)(row_*ROWB + ch_*16);                    \
            size_t go_ = (size_t)(t0 + row_)*En + kofs_ + ch_*8;              \
            ldgsts16(base_ + so_,           Ahi + go_);                       \
            ldgsts16(base_ + OFF_ALO + so_, Alo + go_);                       \
        }                                                                     \
        _Pragma("unroll")                                                     \
        for (int jj = 0; jj < 4; jj++) {                                      \
            int c_ = tid + jj*256;                                            \
            int row_ = c_ >> 2, ch_ = c_ & 3;                                 \
            uint32_t so_ = (uint32_t)(row_*ROWB + ch_*16);                    \
            size_t go_ = (size_t)(f0 + row_)*En + kofs_ + ch_*8;              \
            ldgsts16(base_ + OFF_BHI + so_, Bhi + go_);                       \
            ldgsts16(base_ + OFF_BLO + so_, Blo + go_);                       \
        }                                                                     \
    } while (0)

    float acc[4][8][4] = {};   // [mi][nj][frag]

    LOAD_STAGE(0, 0);
    asm volatile("cp.async.commit_group;");

    for (int i = 0; i < NKI; i++) {
        if (i + 1 < NKI) LOAD_STAGE(i + 1, (i + 1) & 1);
        asm volatile("cp.async.commit_group;");
        asm volatile("cp.async.wait_group 1;");
        __syncthreads();

        const uint32_t base = sb + (uint32_t)(i & 1)*STAGEB;
        const uint32_t lrow = lane & 15;
        const uint32_t lcol = (lane >> 4) << 4;   // 0 or 16 bytes

        #pragma unroll
        for (int kk = 0; kk < 2; kk++) {
            uint32_t ah[4][4], al[4][4];
            #pragma unroll
            for (int mi = 0; mi < 4; mi++) {
                uint32_t addr = base + (uint32_t)(wy*64 + mi*16 + lrow)*ROWB
                              + (uint32_t)kk*32 + lcol;
                LDSM_X4(ah[mi][0], ah[mi][1], ah[mi][2], ah[mi][3], addr);
                LDSM_X4(al[mi][0], al[mi][1], al[mi][2], al[mi][3], addr + OFF_ALO);
            }
            uint32_t bh[8][2], bl[8][2];
            #pragma unroll
            for (int pj = 0; pj < 4; pj++) {
                uint32_t addr = base + OFF_BHI
                              + (uint32_t)(wx*64 + pj*16 + lrow)*ROWB
                              + (uint32_t)kk*32 + lcol;
                uint32_t r0, r1, r2, r3;
                LDSM_X4(r0, r1, r2, r3, addr);
                bh[2*pj][0] = r0; bh[2*pj+1][0] = r1;
                bh[2*pj][1] = r2; bh[2*pj+1][1] = r3;
                LDSM_X4(r0, r1, r2, r3, addr + (OFF_BLO - OFF_BHI));
                bl[2*pj][0] = r0; bl[2*pj+1][0] = r1;
                bl[2*pj][1] = r2; bl[2*pj+1][1] = r3;
            }
            #pragma unroll
            for (int mi = 0; mi < 4; mi++)
                #pragma unroll
                for (int nj = 0; nj < 8; nj++) {
                    mma16816(acc[mi][nj], ah[mi], bh[nj][0], bh[nj][1]);
                    mma16816(acc[mi][nj], ah[mi], bl[nj][0], bl[nj][1]);
                    mma16816(acc[mi][nj], al[mi], bh[nj][0], bh[nj][1]);
                }
        }
        __syncthreads();
    }

    // ---------------- epilogue: direct float2 stores ------------------------
    const int mrow = lane >> 2;          // 0..7
    const int ncol = (lane & 3) * 2;     // 0,2,4,6

    #pragma unroll
    for (int mi = 0; mi < 4; mi++) {
        #pragma unroll
        for (int half = 0; half < 2; half++) {    // c0c1 (m) / c2c3 (m+8)
            int t = t0 + wy*64 + mi*16 + mrow + half*8;
            #pragma unroll
            for (int nj = 0; nj < 8; nj++) {
                int f = f0 + wx*64 + nj*8 + ncol;
                float v0 = acc[mi][nj][half*2 + 0];
                float v1 = acc[mi][nj][half*2 + 1];
                if (mode == 0) {
                    int b = t >> 11, s = t & 2047;
                    int hh = f / 192;
                    int c = f - hh*192;
                    int kind = c >> 6, d = c & 63;
                    float* dst = (kind == 0) ? g_q : ((kind == 1) ? g_k : g_v);
                    float2* p = (float2*)&dst[(((size_t)(b*Hn + hh))*Sn + s)*HDn + d];
                    *p = make_float2(v0, v1);
                } else {
                    float2* p = (float2*)&outp[(size_t)t*En + f];
                    *p = make_float2(v0 + bias[f], v1 + bias[f + 1]);
                }
            }
        }
    }
}

// ---------------------------------------------------------------------------
// Kernel 2: causal flash attention, fp32 SIMT, 64x64 tiles, online softmax.
// Writes output as bf16 hi/lo split (feeds proj GEMM).
// ---------------------------------------------------------------------------
__global__ __launch_bounds__(256) void attn_kernel()
{
    extern __shared__ float sm[];
    float* Qt = sm;               // [64][64]  d-major (transposed)
    float* Kt = sm + 4096;        // [64][64]
    float* Vs = sm + 8192;        // [64][64]  n-major
    float* Ss = sm + 12288;       // [64][65]  padded
    float* rm = Ss + 64*65;
    float* rl = rm + 64;
    float* ra = rl + 64;

    const int tid = threadIdx.x;
    const int tx = tid & 15, ty = tid >> 4;
    const int bh = blockIdx.y;
    const int qt = blockIdx.x;
    const size_t base = (size_t)bh * Sn * HDn;
    const float* Q = g_q + base;
    const float* K = g_k + base;
    const float* V = g_v + base;

    const int lr = tid >> 2;
    const int lc = (tid & 3) * 16;

    {
        const float* qrow = Q + (size_t)(qt*64 + lr)*HDn + lc;
        #pragma unroll
        for (int i = 0; i < 4; i++) {
            float4 v4 = *(const float4*)(qrow + i*4);
            Qt[(lc+i*4+0)*64 + lr] = v4.x;
            Qt[(lc+i*4+1)*64 + lr] = v4.y;
            Qt[(lc+i*4+2)*64 + lr] = v4.z;
            Qt[(lc+i*4+3)*64 + lr] = v4.w;
        }
    }
    if (tid < 64) { rm[tid] = -INFINITY; rl[tid] = 0.f; }

    float acc_o[4][4] = {};

    for (int kt = 0; kt <= qt; kt++) {
        __syncthreads();
        {
            const float* krow = K + (size_t)(kt*64 + lr)*HDn + lc;
            #pragma unroll
            for (int i = 0; i < 4; i++) {
                float4 v4 = *(const float4*)(krow + i*4);
                Kt[(lc+i*4+0)*64 + lr] = v4.x;
                Kt[(lc+i*4+1)*64 + lr] = v4.y;
                Kt[(lc+i*4+2)*64 + lr] = v4.z;
                Kt[(lc+i*4+3)*64 + lr] = v4.w;
            }
            const float* vrow = V + (size_t)(kt*64 + lr)*HDn + lc;
            #pragma unroll
            for (int i = 0; i < 4; i++)
                *(float4*)(Vs + lr*64 + lc + i*4) = *(const float4*)(vrow + i*4);
        }
        __syncthreads();

        float acc_s[4][4] = {};
        #pragma unroll 8
        for (int d = 0; d < 64; d++) {
            float4 a4 = *(const float4*)(Qt + d*64 + ty*4);
            float4 b4 = *(const float4*)(Kt + d*64 + tx*4);
            float a[4] = {a4.x, a4.y, a4.z, a4.w};
            float b[4] = {b4.x, b4.y, b4.z, b4.w};
            #pragma unroll
            for (int i = 0; i < 4; i++)
                #pragma unroll
                for (int j = 0; j < 4; j++)
                    acc_s[i][j] = fmaf(a[i], b[j], acc_s[i][j]);
        }
        #pragma unroll
        for (int i = 0; i < 4; i++) {
            int qi = qt*64 + ty*4 + i;
            #pragma unroll
            for (int j = 0; j < 4; j++) {
                int ki = kt*64 + tx*4 + j;
                float v = acc_s[i][j] * 0.125f;
                Ss[(ty*4+i)*65 + tx*4 + j] = (ki > qi) ? -INFINITY : v;
            }
        }
        __syncthreads();

        if (tid < 64) {
            int r = tid;
            float mold = rm[r];
            float mx = mold;
            #pragma unroll 8
            for (int n = 0; n < 64; n++) mx = fmaxf(mx, Ss[r*65+n]);
            float alpha = expf(mold - mx);
            float sum = 0.f;
            #pragma unroll 8
            for (int n = 0; n < 64; n++) {
                float p = expf(Ss[r*65+n] - mx);
                Ss[r*65+n] = p;
                sum += p;
            }
            rm[r] = mx;
            rl[r] = rl[r]*alpha + sum;
            ra[r] = alpha;
        }
        __syncthreads();

        #pragma unroll
        for (int i = 0; i < 4; i++) {
            float al = ra[ty*4+i];
            #pragma unroll
            for (int j = 0; j < 4; j++) acc_o[i][j] *= al;
        }
        #pragma unroll 4
        for (int n = 0; n < 64; n++) {
            float4 v4 = *(const float4*)(Vs + n*64 + tx*4);
            float vv[4] = {v4.x, v4.y, v4.z, v4.w};
            float p[4];
            #pragma unroll
            for (int i = 0; i < 4; i++) p[i] = Ss[(ty*4+i)*65 + n];
            #pragma unroll
            for (int i = 0; i < 4; i++)
                #pragma unroll
                for (int j = 0; j < 4; j++)
                    acc_o[i][j] = fmaf(p[i], vv[j], acc_o[i][j]);
        }
    }

    const int b = bh >> 4, h = bh & 15;
    #pragma unroll
    for (int i = 0; i < 4; i++) {
        int m = ty*4 + i;
        float inv = 1.f / rl[m];
        int t = b*Sn + qt*64 + m;
        #pragma unroll
        for (int j = 0; j < 4; j++) {
            float o = acc_o[i][j] * inv;
            size_t idx = (size_t)t*En + h*64 + tx*4 + j;
            __nv_bfloat16 hi = __float2bfloat16(o);
            g_att_hi[idx] = hi;
            g_att_lo[idx] = __float2bfloat16(o - __bfloat162float(hi));
        }
    }
}

// ---------------------------------------------------------------------------
extern "C" void kernel_launch(void* const* d_in, const int* in_sizes, int n_in,
                              void* d_out, int out_size)
{
    const float* x      = (const float*)d_in[0];
    const float* w_qkv  = (const float*)d_in[1];
    const float* w_proj = (const float*)d_in[2];
    const float* b_proj = (const float*)d_in[3];
    float* out = (float*)d_out;

    cudaFuncSetAttribute(attn_kernel,
                         cudaFuncAttributeMaxDynamicSharedMemorySize, 66560);
    cudaFuncSetAttribute(gemm_split_kernel,
                         cudaFuncAttributeMaxDynamicSharedMemorySize, GEMM_SMEM);

    __nv_bfloat16 *xhi, *xlo, *wqhi, *wqlo, *wphi, *wplo, *athi, *atlo;
    cudaGetSymbolAddress((void**)&xhi,  g_x_hi);
    cudaGetSymbolAddress((void**)&xlo,  g_x_lo);
    cudaGetSymbolAddress((void**)&wqhi, g_wq_hi);
    cudaGetSymbolAddress((void**)&wqlo, g_wq_lo);
    cudaGetSymbolAddress((void**)&wphi, g_wp_hi);
    cudaGetSymbolAddress((void**)&wplo, g_wp_lo);
    cudaGetSymbolAddress((void**)&athi, g_att_hi);
    cudaGetSymbolAddress((void**)&atlo, g_att_lo);

    // fp32 -> bf16 hi/lo splits
    split_kernel<<<(Tn*En/4 + 255)/256, 256>>>((const float4*)x,
        (__nv_bfloat162*)xhi, (__nv_bfloat162*)xlo, Tn*En/4);
    split_kernel<<<(F1n*En/4 + 255)/256, 256>>>((const float4*)w_qkv,
        (__nv_bfloat162*)wqhi, (__nv_bfloat162*)wqlo, F1n*En/4);
    split_kernel<<<(En*En/4 + 255)/256, 256>>>((const float4*)w_proj,
        (__nv_bfloat162*)wphi, (__nv_bfloat162*)wplo, En*En/4);

    // QKV GEMM (tensor cores, split-bf16 HMMA)
    gemm_split_kernel<<<dim3(F1n/BNn, Tn/BMm), 256, GEMM_SMEM>>>(
        xhi, xlo, wqhi, wqlo, nullptr, nullptr, 0);

    // causal attention (SIMT fp32)
    attn_kernel<<<dim3(Sn/64, Bn*Hn), 256, 66560>>>();

    // output projection (tensor cores) + bias
    gemm_split_kernel<<<dim3(En/BNn, Tn/BMm), 256, GEMM_SMEM>>>(
        athi, atlo, wphi, wplo, out, b_proj, 1);
}

// round 4
// speedup vs baseline: 2.4281x; 1.7645x over previous
#include <cuda_runtime.h>
#include <cuda_bf16.h>
#include <math.h>
#include <stdint.h>

#define Bn 4
#define Sn 2048
#define En 1024
#define Hn 16
#define HDn 64
#define Tn (Bn*Sn)        // 8192 tokens
#define F1n (3*En)        // 3072

#define QSCALE 0.180336880436f   // 0.125 * log2(e): scores land in exp2 domain

// ---------------------------------------------------------------------------
// Scratch (static device globals — allocation-free per harness rules)
// ---------------------------------------------------------------------------
__device__ __nv_bfloat16 g_qh[(size_t)Bn*Hn*Sn*HDn];  // [b*H+h][s][d] (scaled)
__device__ __nv_bfloat16 g_ql[(size_t)Bn*Hn*Sn*HDn];
__device__ __nv_bfloat16 g_kh[(size_t)Bn*Hn*Sn*HDn];
__device__ __nv_bfloat16 g_kl[(size_t)Bn*Hn*Sn*HDn];
__device__ __nv_bfloat16 g_vh[(size_t)Bn*Hn*Sn*HDn];
__device__ __nv_bfloat16 g_vl[(size_t)Bn*Hn*Sn*HDn];
__device__ __nv_bfloat16 g_x_hi[(size_t)Tn*En];
__device__ __nv_bfloat16 g_x_lo[(size_t)Tn*En];
__device__ __nv_bfloat16 g_wq_hi[(size_t)F1n*En];
__device__ __nv_bfloat16 g_wq_lo[(size_t)F1n*En];
__device__ __nv_bfloat16 g_wp_hi[(size_t)En*En];
__device__ __nv_bfloat16 g_wp_lo[(size_t)En*En];
__device__ __nv_bfloat16 g_att_hi[(size_t)Tn*En];
__device__ __nv_bfloat16 g_att_lo[(size_t)Tn*En];

// ---------------------------------------------------------------------------
// Helpers (baseline PTX only — no 'a'-suffix arch features)
// ---------------------------------------------------------------------------
__device__ __forceinline__ uint32_t smem_u32(const void* p) {
    uint32_t a;
    asm("{ .reg .u64 t; cvta.to.shared.u64 t, %1; cvt.u32.u64 %0, t; }" : "=r"(a) : "l"(p));
    return a;
}

__device__ __forceinline__ void ldgsts16(uint32_t dst, const void* src) {
    asm volatile("cp.async.cg.shared.global [%0], [%1], 16;" :: "r"(dst), "l"(src));
}

#define LDSM_X4(r0, r1, r2, r3, addr) \
    asm volatile("ldmatrix.sync.aligned.m8n8.x4.shared.b16 {%0,%1,%2,%3}, [%4];" \
        : "=r"(r0), "=r"(r1), "=r"(r2), "=r"(r3) : "r"(addr))

#define LDSM_X4_T(r0, r1, r2, r3, addr) \
    asm volatile("ldmatrix.sync.aligned.m8n8.x4.trans.shared.b16 {%0,%1,%2,%3}, [%4];" \
        : "=r"(r0), "=r"(r1), "=r"(r2), "=r"(r3) : "r"(addr))

__device__ __forceinline__ void mma16816(float c[4], const uint32_t a[4],
                                         uint32_t b0, uint32_t b1) {
    asm volatile(
        "mma.sync.aligned.m16n8k16.row.col.f32.bf16.bf16.f32 "
        "{%0,%1,%2,%3}, {%4,%5,%6,%7}, {%8,%9}, {%0,%1,%2,%3};"
        : "+f"(c[0]), "+f"(c[1]), "+f"(c[2]), "+f"(c[3])
        : "r"(a[0]), "r"(a[1]), "r"(a[2]), "r"(a[3]), "r"(b0), "r"(b1));
}

__device__ __forceinline__ float ex2f(float x) {
    float r; asm("ex2.approx.ftz.f32 %0, %1;" : "=f"(r) : "f"(x)); return r;
}

__device__ __forceinline__ uint32_t pack_bf2(float a, float b) {
    __nv_bfloat162 h = __floats2bfloat162_rn(a, b);
    return *reinterpret_cast<uint32_t*>(&h);
}

// ---------------------------------------------------------------------------
// Kernel 0: fp32 -> (bf16 hi, bf16 lo) split, float4-vectorized
// ---------------------------------------------------------------------------
__global__ __launch_bounds__(256) void split_kernel(
    const float4* __restrict__ src, __nv_bfloat162* __restrict__ hi,
    __nv_bfloat162* __restrict__ lo, int n4)
{
    int i = blockIdx.x * 256 + threadIdx.x;
    if (i >= n4) return;
    float4 v = src[i];
    __nv_bfloat16 h0 = __float2bfloat16(v.x), h1 = __float2bfloat16(v.y);
    __nv_bfloat16 h2 = __float2bfloat16(v.z), h3 = __float2bfloat16(v.w);
    __nv_bfloat162 a; a.x = h0; a.y = h1;
    __nv_bfloat162 b; b.x = h2; b.y = h3;
    __nv_bfloat162 c; c.x = __float2bfloat16(v.x - __bfloat162float(h0));
    c.y = __float2bfloat16(v.y - __bfloat162float(h1));
    __nv_bfloat162 d; d.x = __float2bfloat16(v.z - __bfloat162float(h2));
    d.y = __float2bfloat16(v.w - __bfloat162float(h3));
    hi[2*i] = a; hi[2*i+1] = b;
    lo[2*i] = c; lo[2*i+1] = d;
}

// ---------------------------------------------------------------------------
// Split-bf16 HMMA GEMM.  C[r][f] = sum_k A[r][k]*B[f][k]   (K = 1024)
// BM=128, BN=256, BK=32. 8 warps, each a 64x64 tile.
//   mode 0: split C into bf16 hi/lo head-major q/k/v (q pre-scaled)
//   mode 1: C + bias -> out (fp32, row-major)
// ---------------------------------------------------------------------------
#define BMm 128
#define BNn 256
#define BKk 32
#define NKI (En/BKk)            // 32
#define ROWB 80                 // padded row stride in bytes (32 bf16 + 8 pad)
#define OFF_ALO 10240           // 128*80
#define OFF_BHI 20480
#define OFF_BLO 40960
#define STAGEB  61440
#define GEMM_SMEM (2*STAGEB)    // 122880

__global__ __launch_bounds__(256) void gemm_split_kernel(
    const __nv_bfloat16* __restrict__ Ahi, const __nv_bfloat16* __restrict__ Alo,
    const __nv_bfloat16* __restrict__ Bhi, const __nv_bfloat16* __restrict__ Blo,
    float* __restrict__ outp, const float* __restrict__ bias, int mode)
{
    extern __shared__ char dsm[];
    const uint32_t sb = smem_u32(dsm);
    const int tid = threadIdx.x;
    const int wid = tid >> 5, lane = tid & 31;
    const int wy = wid & 1, wx = wid >> 1;
    const int t0 = blockIdx.y * BMm, f0 = blockIdx.x * BNn;

    #define LOAD_STAGE(ki, s) do {                                            \
        uint32_t base_ = sb + (uint32_t)(s)*STAGEB;                           \
        int kofs_ = (ki)*BKk;                                                 \
        _Pragma("unroll")                                                     \
        for (int jj = 0; jj < 2; jj++) {                                      \
            int c_ = tid + jj*256;                                            \
            int row_ = c_ >> 2, ch_ = c_ & 3;                                 \
            uint32_t so_ = (uint32_t)(row_*ROWB + ch_*16);                    \
            size_t go_ = (size_t)(t0 + row_)*En + kofs_ + ch_*8;              \
            ldgsts16(base_ + so_,           Ahi + go_);                       \
            ldgsts16(base_ + OFF_ALO + so_, Alo + go_);                       \
        }                                                                     \
        _Pragma("unroll")                                                     \
        for (int jj = 0; jj < 4; jj++) {                                      \
            int c_ = tid + jj*256;                                            \
            int row_ = c_ >> 2, ch_ = c_ & 3;                                 \
            uint32_t so_ = (uint32_t)(row_*ROWB + ch_*16);                    \
            size_t go_ = (size_t)(f0 + row_)*En + kofs_ + ch_*8;              \
            ldgsts16(base_ + OFF_BHI + so_, Bhi + go_);                       \
            ldgsts16(base_ + OFF_BLO + so_, Blo + go_);                       \
        }                                                                     \
    } while (0)

    float acc[4][8][4] = {};

    LOAD_STAGE(0, 0);
    asm volatile("cp.async.commit_group;");

    for (int i = 0; i < NKI; i++) {
        if (i + 1 < NKI) LOAD_STAGE(i + 1, (i + 1) & 1);
        asm volatile("cp.async.commit_group;");
        asm volatile("cp.async.wait_group 1;");
        __syncthreads();

        const uint32_t base = sb + (uint32_t)(i & 1)*STAGEB;
        const uint32_t lrow = lane & 15;
        const uint32_t lcol = (lane >> 4) << 4;

        #pragma unroll
        for (int kk = 0; kk < 2; kk++) {
            uint32_t ah[4][4], al[4][4];
            #pragma unroll
            for (int mi = 0; mi < 4; mi++) {
                uint32_t addr = base + (uint32_t)(wy*64 + mi*16 + lrow)*ROWB
                              + (uint32_t)kk*32 + lcol;
                LDSM_X4(ah[mi][0], ah[mi][1], ah[mi][2], ah[mi][3], addr);
                LDSM_X4(al[mi][0], al[mi][1], al[mi][2], al[mi][3], addr + OFF_ALO);
            }
            uint32_t bh[8][2], bl[8][2];
            #pragma unroll
            for (int pj = 0; pj < 4; pj++) {
                uint32_t addr = base + OFF_BHI
                              + (uint32_t)(wx*64 + pj*16 + lrow)*ROWB
                              + (uint32_t)kk*32 + lcol;
                uint32_t r0, r1, r2, r3;
                LDSM_X4(r0, r1, r2, r3, addr);
                bh[2*pj][0] = r0; bh[2*pj+1][0] = r1;
                bh[2*pj][1] = r2; bh[2*pj+1][1] = r3;
                LDSM_X4(r0, r1, r2, r3, addr + (OFF_BLO - OFF_BHI));
                bl[2*pj][0] = r0; bl[2*pj+1][0] = r1;
                bl[2*pj][1] = r2; bl[2*pj+1][1] = r3;
            }
            #pragma unroll
            for (int mi = 0; mi < 4; mi++)
                #pragma unroll
                for (int nj = 0; nj < 8; nj++) {
                    mma16816(acc[mi][nj], ah[mi], bh[nj][0], bh[nj][1]);
                    mma16816(acc[mi][nj], ah[mi], bl[nj][0], bl[nj][1]);
                    mma16816(acc[mi][nj], al[mi], bh[nj][0], bh[nj][1]);
                }
        }
        __syncthreads();
    }

    // ---------------- epilogue ----------------------------------------------
    const int mrow = lane >> 2;
    const int ncol = (lane & 3) * 2;

    #pragma unroll
    for (int mi = 0; mi < 4; mi++) {
        #pragma unroll
        for (int half = 0; half < 2; half++) {
            int t = t0 + wy*64 + mi*16 + mrow + half*8;
            #pragma unroll
            for (int nj = 0; nj < 8; nj++) {
                int f = f0 + wx*64 + nj*8 + ncol;
                float v0 = acc[mi][nj][half*2 + 0];
                float v1 = acc[mi][nj][half*2 + 1];
                if (mode == 0) {
                    int bidx = t >> 11, sidx = t & 2047;
                    int hh = f / 192;
                    int c = f - hh*192;
                    int kind = c >> 6, d = c & 63;
                    if (kind == 0) { v0 *= QSCALE; v1 *= QSCALE; }
                    __nv_bfloat16* hp = (kind == 0) ? g_qh : ((kind == 1) ? g_kh : g_vh);
                    __nv_bfloat16* lp = (kind == 0) ? g_ql : ((kind == 1) ? g_kl : g_vl);
                    size_t idx = (((size_t)(bidx*Hn + hh))*Sn + sidx)*HDn + d;
                    __nv_bfloat162 h2 = __floats2bfloat162_rn(v0, v1);
                    __nv_bfloat162 l2 = __floats2bfloat162_rn(
                        v0 - __bfloat162float(h2.x), v1 - __bfloat162float(h2.y));
                    *(__nv_bfloat162*)(hp + idx) = h2;
                    *(__nv_bfloat162*)(lp + idx) = l2;
                } else {
                    float2* p = (float2*)&outp[(size_t)t*En + f];
                    *p = make_float2(v0 + bias[f], v1 + bias[f + 1]);
                }
            }
        }
    }
}

// ---------------------------------------------------------------------------
// Kernel 2: causal flash attention, split-bf16 HMMA, FA2 register layout.
// Block: 128 q-rows (8 warps x m16), kv tiles of 64, double-buffered cp.async.
// Scores arrive in exp2 domain (scale*log2e folded into Q).
// ---------------------------------------------------------------------------
#define AROWB 144               // 64 bf16 = 128B data + 16B pad (16B-aligned rows)
#define A_QH 0
#define A_QL (128*AROWB)        // 18432
#define A_ST0 (2*128*AROWB)     // 36864
#define A_KH 0
#define A_KL (64*AROWB)         // 9216
#define A_VH (2*64*AROWB)       // 18432
#define A_VL (3*64*AROWB)       // 27648
#define A_STAGE (4*64*AROWB)    // 36864
#define ATTN_SMEM (A_ST0 + 2*A_STAGE)   // 110592

__global__ __launch_bounds__(256) void attn_mma_kernel()
{
    extern __shared__ char dsm[];
    const uint32_t sb = smem_u32(dsm);
    const int tid = threadIdx.x;
    const int wid = tid >> 5, lane = tid & 31;
    const int qt = blockIdx.x, bh = blockIdx.y;
    const int q0 = qt * 128;
    const size_t gbase = (size_t)bh * Sn * HDn;
    const int nk = 2*qt + 2;

    #define LOAD_KV(kt_, s_) do {                                             \
        uint32_t st_ = sb + A_ST0 + (uint32_t)(s_)*A_STAGE;                   \
        int kv_ = (kt_)*64;                                                   \
        _Pragma("unroll")                                                     \
        for (int j_ = 0; j_ < 2; j_++) {                                      \
            int c_ = tid + j_*256;                                            \
            int row_ = c_ >> 3, ch_ = c_ & 7;                                 \
            uint32_t so_ = (uint32_t)(row_*AROWB + ch_*16);                   \
            size_t go_ = gbase + (size_t)(kv_ + row_)*HDn + ch_*8;            \
            ldgsts16(st_ + A_KH + so_, g_kh + go_);                           \
            ldgsts16(st_ + A_KL + so_, g_kl + go_);                           \
            ldgsts16(st_ + A_VH + so_, g_vh + go_);                           \
            ldgsts16(st_ + A_VL + so_, g_vl + go_);                           \
        } } while (0)

    // Q tile (hi/lo) -> smem
    #pragma unroll
    for (int j = 0; j < 4; j++) {
        int c = tid + j*256;
        int row = c >> 3, ch = c & 7;
        uint32_t so = (uint32_t)(row*AROWB + ch*16);
        size_t go = gbase + (size_t)(q0 + row)*HDn + ch*8;
        ldgsts16(sb + A_QH + so, g_qh + go);
        ldgsts16(sb + A_QL + so, g_ql + go);
    }
    asm volatile("cp.async.commit_group;");
    LOAD_KV(0, 0);
    asm volatile("cp.async.commit_group;");
    if (nk > 1) LOAD_KV(1, 1);
    asm volatile("cp.async.commit_group;");

    asm volatile("cp.async.wait_group 2;");   // Q ready
    __syncthreads();

    // Q fragments (persist in registers)
    uint32_t qh_[4][4], ql_[4][4];
    {
        uint32_t r_ = (uint32_t)(wid*16 + (lane & 15));
        uint32_t cb = (uint32_t)((lane >> 4) << 4);
        #pragma unroll
        for (int kk = 0; kk < 4; kk++) {
            uint32_t addr = sb + A_QH + r_*AROWB + (uint32_t)kk*32 + cb;
            LDSM_X4(qh_[kk][0], qh_[kk][1], qh_[kk][2], qh_[kk][3], addr);
            LDSM_X4(ql_[kk][0], ql_[kk][1], ql_[kk][2], ql_[kk][3], addr + (A_QL - A_QH));
        }
    }

    float m0 = -INFINITY, m1 = -INFINITY, l0 = 0.f, l1 = 0.f;
    float acc[8][4] = {};

    for (int kt = 0; kt < nk; kt++) {
        asm volatile("cp.async.wait_group 1;");
        __syncthreads();

        const uint32_t st = sb + A_ST0 + (uint32_t)(kt & 1)*A_STAGE;
        const int kv0 = kt * 64;

        // ---- S = Q @ K^T (3-term split) ----
        float s[8][4] = {};
        {
            uint32_t r_ = (uint32_t)(lane & 15);
            uint32_t cb = (uint32_t)((lane >> 4) << 4);
            #pragma unroll
            for (int kk = 0; kk < 4; kk++) {
                uint32_t kh[8][2], kl[8][2];
                #pragma unroll
                for (int pj = 0; pj < 4; pj++) {
                    uint32_t addr = st + A_KH + (uint32_t)(pj*16 + r_)*AROWB
                                  + (uint32_t)kk*32 + cb;
                    uint32_t r0, r1, r2, r3;
                    LDSM_X4(r0, r1, r2, r3, addr);
                    kh[2*pj][0]=r0; kh[2*pj][1]=r2; kh[2*pj+1][0]=r1; kh[2*pj+1][1]=r3;
                    LDSM_X4(r0, r1, r2, r3, addr + (A_KL - A_KH));
                    kl[2*pj][0]=r0; kl[2*pj][1]=r2; kl[2*pj+1][0]=r1; kl[2*pj+1][1]=r3;
                }
                #pragma unroll
                for (int nj = 0; nj < 8; nj++) {
                    mma16816(s[nj], qh_[kk], kh[nj][0], kh[nj][1]);
                    mma16816(s[nj], qh_[kk], kl[nj][0], kl[nj][1]);
                    mma16816(s[nj], ql_[kk], kh[nj][0], kh[nj][1]);
                }
            }
        }

        // ---- causal mask ----
        const int rbase = q0 + wid*16 + (lane >> 2);
        if (kv0 + 63 > q0 + wid*16) {
            #pragma unroll
            for (int nj = 0; nj < 8; nj++)
                #pragma unroll
                for (int i = 0; i < 4; i++) {
                    int col = kv0 + nj*8 + (lane & 3)*2 + (i & 1);
                    int row = rbase + (i >> 1)*8;
                    if (col > row) s[nj][i] = -INFINITY;
                }
        }

        // ---- online softmax (exp2 domain) ----
        float mx0 = -INFINITY, mx1 = -INFINITY;
        #pragma unroll
        for (int nj = 0; nj < 8; nj++) {
            mx0 = fmaxf(mx0, fmaxf(s[nj][0], s[nj][1]));
            mx1 = fmaxf(mx1, fmaxf(s[nj][2], s[nj][3]));
        }
        mx0 = fmaxf(mx0, __shfl_xor_sync(0xffffffffu, mx0, 1));
        mx0 = fmaxf(mx0, __shfl_xor_sync(0xffffffffu, mx0, 2));
        mx1 = fmaxf(mx1, __shfl_xor_sync(0xffffffffu, mx1, 1));
        mx1 = fmaxf(mx1, __shfl_xor_sync(0xffffffffu, mx1, 2));
        float mn0 = fmaxf(m0, mx0), mn1 = fmaxf(m1, mx1);
        float al0 = ex2f(m0 - mn0), al1 = ex2f(m1 - mn1);
        m0 = mn0; m1 = mn1;
        float rs0 = 0.f, rs1 = 0.f;
        #pragma unroll
        for (int nj = 0; nj < 8; nj++) {
            float p0 = ex2f(s[nj][0] - mn0), p1 = ex2f(s[nj][1] - mn0);
            float p2 = ex2f(s[nj][2] - mn1), p3 = ex2f(s[nj][3] - mn1);
            s[nj][0] = p0; s[nj][1] = p1; s[nj][2] = p2; s[nj][3] = p3;
            rs0 += p0 + p1; rs1 += p2 + p3;
        }
        rs0 += __shfl_xor_sync(0xffffffffu, rs0, 1);
        rs0 += __shfl_xor_sync(0xffffffffu, rs0, 2);
        rs1 += __shfl_xor_sync(0xffffffffu, rs1, 1);
        rs1 += __shfl_xor_sync(0xffffffffu, rs1, 2);
        l0 = l0*al0 + rs0;
        l1 = l1*al1 + rs1;
        #pragma unroll
        for (int nj = 0; nj < 8; nj++) {
            acc[nj][0] *= al0; acc[nj][1] *= al0;
            acc[nj][2] *= al1; acc[nj][3] *= al1;
        }

        // ---- O += P @ V (3-term split; V frags via ldmatrix.trans) ----
        {
            uint32_t rr = (uint32_t)(((lane >> 4) << 3) + (lane & 7));
            uint32_t cb = (uint32_t)(((lane >> 3) & 1) << 4);
            #pragma unroll
            for (int kk2 = 0; kk2 < 4; kk2++) {
                uint32_t pah[4], pal[4];
                #pragma unroll
                for (int tp = 0; tp < 2; tp++) {
                    int t_ = 2*kk2 + tp;
                    float p0 = s[t_][0], p1 = s[t_][1], p2 = s[t_][2], p3 = s[t_][3];
                    __nv_bfloat162 h01 = __floats2bfloat162_rn(p0, p1);
                    __nv_bfloat162 h23 = __floats2bfloat162_rn(p2, p3);
                    pah[2*tp+0] = *reinterpret_cast<uint32_t*>(&h01);
                    pah[2*tp+1] = *reinterpret_cast<uint32_t*>(&h23);
                    pal[2*tp+0] = pack_bf2(p0 - __bfloat162float(h01.x),
                                           p1 - __bfloat162float(h01.y));
                    pal[2*tp+1] = pack_bf2(p2 - __bfloat162float(h23.x),
                                           p3 - __bfloat162float(h23.y));
                }
                uint32_t bvh[8][2], bvl[8][2];
                #pragma unroll
                for (int dj = 0; dj < 4; dj++) {
                    uint32_t addr = st + A_VH + (uint32_t)(kk2*16 + rr)*AROWB
                                  + (uint32_t)dj*32 + cb;
                    uint32_t r0, r1, r2, r3;
                    LDSM_X4_T(r0, r1, r2, r3, addr);
                    bvh[2*dj][0]=r0; bvh[2*dj][1]=r2; bvh[2*dj+1][0]=r1; bvh[2*dj+1][1]=r3;
                    LDSM_X4_T(r0, r1, r2, r3, addr + (A_VL - A_VH));
                    bvl[2*dj][0]=r0; bvl[2*dj][1]=r2; bvl[2*dj+1][0]=r1; bvl[2*dj+1][1]=r3;
                }
                #pragma unroll
                for (int nj = 0; nj < 8; nj++) {
                    mma16816(acc[nj], pah, bvh[nj][0], bvh[nj][1]);
                    mma16816(acc[nj], pah, bvl[nj][0], bvl[nj][1]);
                    mma16816(acc[nj], pal, bvh[nj][0], bvh[nj][1]);
                }
            }
        }

        __syncthreads();
        if (kt + 2 < nk) LOAD_KV(kt + 2, kt & 1);
        asm volatile("cp.async.commit_group;");
    }

    // ---- epilogue: normalize, write bf16 hi/lo for proj GEMM ----
    float inv0 = 1.f / l0, inv1 = 1.f / l1;
    const int b = bh >> 4, h = bh & 15;
    const int r0_ = q0 + wid*16 + (lane >> 2);
    #pragma unroll
    for (int nj = 0; nj < 8; nj++) {
        int d = nj*8 + (lane & 3)*2;
        size_t i0 = (size_t)(b*Sn + r0_)*En + h*HDn + d;
        size_t i1 = i0 + (size_t)8*En;
        float o0 = acc[nj][0]*inv0, o1 = acc[nj][1]*inv0;
        float o2 = acc[nj][2]*inv1, o3 = acc[nj][3]*inv1;
        __nv_bfloat162 h01 = __floats2bfloat162_rn(o0, o1);
        __nv_bfloat162 l01 = __floats2bfloat162_rn(o0 - __bfloat162float(h01.x),
                                                   o1 - __bfloat162float(h01.y));
        __nv_bfloat162 h23 = __floats2bfloat162_rn(o2, o3);
        __nv_bfloat162 l23 = __floats2bfloat162_rn(o2 - __bfloat162float(h23.x),
                                                   o3 - __bfloat162float(h23.y));
        *(__nv_bfloat162*)(g_att_hi + i0) = h01;
        *(__nv_bfloat162*)(g_att_lo + i0) = l01;
        *(__nv_bfloat162*)(g_att_hi + i1) = h23;
        *(__nv_bfloat162*)(g_att_lo + i1) = l23;
    }
}

// ---------------------------------------------------------------------------
extern "C" void kernel_launch(void* const* d_in, const int* in_sizes, int n_in,
                              void* d_out, int out_size)
{
    const float* x      = (const float*)d_in[0];
    const float* w_qkv  = (const float*)d_in[1];
    const float* w_proj = (const float*)d_in[2];
    const float* b_proj = (const float*)d_in[3];
    float* out = (float*)d_out;

    cudaFuncSetAttribute(gemm_split_kernel,
                         cudaFuncAttributeMaxDynamicSharedMemorySize, GEMM_SMEM);
    cudaFuncSetAttribute(attn_mma_kernel,
                         cudaFuncAttributeMaxDynamicSharedMemorySize, ATTN_SMEM);

    __nv_bfloat16 *xhi, *xlo, *wqhi, *wqlo, *wphi, *wplo, *athi, *atlo;
    cudaGetSymbolAddress((void**)&xhi,  g_x_hi);
    cudaGetSymbolAddress((void**)&xlo,  g_x_lo);
    cudaGetSymbolAddress((void**)&wqhi, g_wq_hi);
    cudaGetSymbolAddress((void**)&wqlo, g_wq_lo);
    cudaGetSymbolAddress((void**)&wphi, g_wp_hi);
    cudaGetSymbolAddress((void**)&wplo, g_wp_lo);
    cudaGetSymbolAddress((void**)&athi, g_att_hi);
    cudaGetSymbolAddress((void**)&atlo, g_att_lo);

    // fp32 -> bf16 hi/lo splits
    split_kernel<<<(Tn*En/4 + 255)/256, 256>>>((const float4*)x,
        (__nv_bfloat162*)xhi, (__nv_bfloat162*)xlo, Tn*En/4);
    split_kernel<<<(F1n*En/4 + 255)/256, 256>>>((const float4*)w_qkv,
        (__nv_bfloat162*)wqhi, (__nv_bfloat162*)wqlo, F1n*En/4);
    split_kernel<<<(En*En/4 + 255)/256, 256>>>((const float4*)w_proj,
        (__nv_bfloat162*)wphi, (__nv_bfloat162*)wplo, En*En/4);

    // QKV GEMM (split-bf16 HMMA) -> bf16 hi/lo Q/K/V (Q pre-scaled)
    gemm_split_kernel<<<dim3(F1n/BNn, Tn/BMm), 256, GEMM_SMEM>>>(
        xhi, xlo, wqhi, wqlo, nullptr, nullptr, 0);

    // causal flash attention (split-bf16 HMMA)
    attn_mma_kernel<<<dim3(Sn/128, Bn*Hn), 256, ATTN_SMEM>>>();

    // output projection (split-bf16 HMMA) + bias
    gemm_split_kernel<<<dim3(En/BNn, Tn/BMm), 256, GEMM_SMEM>>>(
        athi, atlo, wphi, wplo, out, b_proj, 1);
}

// round 5
// speedup vs baseline: 2.6815x; 1.1044x over previous
#include <cuda_runtime.h>
#include <cuda_bf16.h>
#include <math.h>
#include <stdint.h>

#define Bn 4
#define Sn 2048
#define En 1024
#define Hn 16
#define HDn 64
#define Tn (Bn*Sn)        // 8192 tokens
#define F1n (3*En)        // 3072

#define QSCALE 0.180336880436f   // 0.125 * log2(e): scores land in exp2 domain

// ---------------------------------------------------------------------------
// Scratch (static device globals — allocation-free per harness rules)
// ---------------------------------------------------------------------------
__device__ __nv_bfloat16 g_qh[(size_t)Bn*Hn*Sn*HDn];  // [b*H+h][s][d] (scaled)
__device__ __nv_bfloat16 g_ql[(size_t)Bn*Hn*Sn*HDn];
__device__ __nv_bfloat16 g_kh[(size_t)Bn*Hn*Sn*HDn];
__device__ __nv_bfloat16 g_kl[(size_t)Bn*Hn*Sn*HDn];
__device__ __nv_bfloat16 g_vh[(size_t)Bn*Hn*Sn*HDn];
__device__ __nv_bfloat16 g_vl[(size_t)Bn*Hn*Sn*HDn];
__device__ __nv_bfloat16 g_x_hi[(size_t)Tn*En];
__device__ __nv_bfloat16 g_x_lo[(size_t)Tn*En];
__device__ __nv_bfloat16 g_wq_hi[(size_t)F1n*En];
__device__ __nv_bfloat16 g_wq_lo[(size_t)F1n*En];
__device__ __nv_bfloat16 g_wp_hi[(size_t)En*En];
__device__ __nv_bfloat16 g_wp_lo[(size_t)En*En];
__device__ __nv_bfloat16 g_att_hi[(size_t)Tn*En];
__device__ __nv_bfloat16 g_att_lo[(size_t)Tn*En];

// ---------------------------------------------------------------------------
// Helpers (baseline PTX only — no 'a'-suffix arch features)
// ---------------------------------------------------------------------------
__device__ __forceinline__ uint32_t smem_u32(const void* p) {
    uint32_t a;
    asm("{ .reg .u64 t; cvta.to.shared.u64 t, %1; cvt.u32.u64 %0, t; }" : "=r"(a) : "l"(p));
    return a;
}

__device__ __forceinline__ void ldgsts16(uint32_t dst, const void* src) {
    asm volatile("cp.async.cg.shared.global [%0], [%1], 16;" :: "r"(dst), "l"(src));
}

#define LDSM_X4(r0, r1, r2, r3, addr) \
    asm volatile("ldmatrix.sync.aligned.m8n8.x4.shared.b16 {%0,%1,%2,%3}, [%4];" \
        : "=r"(r0), "=r"(r1), "=r"(r2), "=r"(r3) : "r"(addr))

#define LDSM_X4_T(r0, r1, r2, r3, addr) \
    asm volatile("ldmatrix.sync.aligned.m8n8.x4.trans.shared.b16 {%0,%1,%2,%3}, [%4];" \
        : "=r"(r0), "=r"(r1), "=r"(r2), "=r"(r3) : "r"(addr))

__device__ __forceinline__ void mma16816(float c[4], const uint32_t a[4],
                                         uint32_t b0, uint32_t b1) {
    asm volatile(
        "mma.sync.aligned.m16n8k16.row.col.f32.bf16.bf16.f32 "
        "{%0,%1,%2,%3}, {%4,%5,%6,%7}, {%8,%9}, {%0,%1,%2,%3};"
        : "+f"(c[0]), "+f"(c[1]), "+f"(c[2]), "+f"(c[3])
        : "r"(a[0]), "r"(a[1]), "r"(a[2]), "r"(a[3]), "r"(b0), "r"(b1));
}

__device__ __forceinline__ float ex2f(float x) {
    float r; asm("ex2.approx.ftz.f32 %0, %1;" : "=f"(r) : "f"(x)); return r;
}

__device__ __forceinline__ uint32_t pack_bf2(float a, float b) {
    __nv_bfloat162 h = __floats2bfloat162_rn(a, b);
    return *reinterpret_cast<uint32_t*>(&h);
}

// ---------------------------------------------------------------------------
// Kernel 0: fp32 -> (bf16 hi, bf16 lo) split, float4-vectorized
// ---------------------------------------------------------------------------
__global__ __launch_bounds__(256) void split_kernel(
    const float4* __restrict__ src, __nv_bfloat162* __restrict__ hi,
    __nv_bfloat162* __restrict__ lo, int n4)
{
    int i = blockIdx.x * 256 + threadIdx.x;
    if (i >= n4) return;
    float4 v = src[i];
    __nv_bfloat16 h0 = __float2bfloat16(v.x), h1 = __float2bfloat16(v.y);
    __nv_bfloat16 h2 = __float2bfloat16(v.z), h3 = __float2bfloat16(v.w);
    __nv_bfloat162 a; a.x = h0; a.y = h1;
    __nv_bfloat162 b; b.x = h2; b.y = h3;
    __nv_bfloat162 c; c.x = __float2bfloat16(v.x - __bfloat162float(h0));
    c.y = __float2bfloat16(v.y - __bfloat162float(h1));
    __nv_bfloat162 d; d.x = __float2bfloat16(v.z - __bfloat162float(h2));
    d.y = __float2bfloat16(v.w - __bfloat162float(h3));
    hi[2*i] = a; hi[2*i+1] = b;
    lo[2*i] = c; lo[2*i+1] = d;
}

// ---------------------------------------------------------------------------
// Split-bf16 HMMA GEMM.  C[r][f] = sum_k A[r][k]*B[f][k]   (K = 1024)
// BM=128, BN=128, BK=32. 8 warps (2x4), each a 64x32 tile.
// 2-stage cp.async double buffer; __launch_bounds__(256,2) -> 2 CTAs/SM.
//   mode 0: split C into bf16 hi/lo head-major q/k/v (q pre-scaled)
//   mode 1: C + bias -> out (fp32, row-major)
// ---------------------------------------------------------------------------
#define BMm 128
#define BNn 128
#define BKk 32
#define NKI (En/BKk)            // 32
#define ROWB 80                 // padded row stride in bytes (32 bf16 + 8 pad)
#define OFF_ALO 10240           // 128*80
#define OFF_BHI 20480
#define OFF_BLO 30720
#define STAGEB  40960
#define GEMM_SMEM (2*STAGEB)    // 81920

__global__ __launch_bounds__(256, 2) void gemm_split_kernel(
    const __nv_bfloat16* __restrict__ Ahi, const __nv_bfloat16* __restrict__ Alo,
    const __nv_bfloat16* __restrict__ Bhi, const __nv_bfloat16* __restrict__ Blo,
    float* __restrict__ outp, const float* __restrict__ bias, int mode)
{
    extern __shared__ char dsm[];
    const uint32_t sb = smem_u32(dsm);
    const int tid = threadIdx.x;
    const int wid = tid >> 5, lane = tid & 31;
    const int wy = wid & 1, wx = wid >> 1;         // warp tile: (wy*64, wx*32)
    const int t0 = blockIdx.y * BMm, f0 = blockIdx.x * BNn;

    // stage = 40KB: A hi/lo + B hi/lo, each 128 rows x 32 bf16 (80B rows)
    #define LOAD_STAGE(ki, s) do {                                            \
        uint32_t base_ = sb + (uint32_t)(s)*STAGEB;                           \
        int kofs_ = (ki)*BKk;                                                 \
        _Pragma("unroll")                                                     \
        for (int jj = 0; jj < 2; jj++) {                                      \
            int c_ = tid + jj*256;                                            \
            int row_ = c_ >> 2, ch_ = c_ & 3;                                 \
            uint32_t so_ = (uint32_t)(row_*ROWB + ch_*16);                    \
            size_t ga_ = (size_t)(t0 + row_)*En + kofs_ + ch_*8;              \
            size_t gb_ = (size_t)(f0 + row_)*En + kofs_ + ch_*8;              \
            ldgsts16(base_ + so_,           Ahi + ga_);                       \
            ldgsts16(base_ + OFF_ALO + so_, Alo + ga_);                       \
            ldgsts16(base_ + OFF_BHI + so_, Bhi + gb_);                       \
            ldgsts16(base_ + OFF_BLO + so_, Blo + gb_);                       \
        }                                                                     \
    } while (0)

    float acc[4][4][4] = {};   // [mi][nj][frag]

    LOAD_STAGE(0, 0);
    asm volatile("cp.async.commit_group;");

    for (int i = 0; i < NKI; i++) {
        if (i + 1 < NKI) LOAD_STAGE(i + 1, (i + 1) & 1);
        asm volatile("cp.async.commit_group;");
        asm volatile("cp.async.wait_group 1;");
        __syncthreads();

        const uint32_t base = sb + (uint32_t)(i & 1)*STAGEB;
        const uint32_t lrow = lane & 15;
        const uint32_t lcol = (lane >> 4) << 4;

        #pragma unroll
        for (int kk = 0; kk < 2; kk++) {
            uint32_t ah[4][4], al[4][4];
            #pragma unroll
            for (int mi = 0; mi < 4; mi++) {
                uint32_t addr = base + (uint32_t)(wy*64 + mi*16 + lrow)*ROWB
                              + (uint32_t)kk*32 + lcol;
                LDSM_X4(ah[mi][0], ah[mi][1], ah[mi][2], ah[mi][3], addr);
                LDSM_X4(al[mi][0], al[mi][1], al[mi][2], al[mi][3], addr + OFF_ALO);
            }
            uint32_t bh[4][2], bl[4][2];
            #pragma unroll
            for (int pj = 0; pj < 2; pj++) {
                uint32_t addr = base + OFF_BHI
                              + (uint32_t)(wx*32 + pj*16 + lrow)*ROWB
                              + (uint32_t)kk*32 + lcol;
                uint32_t r0, r1, r2, r3;
                LDSM_X4(r0, r1, r2, r3, addr);
                bh[2*pj][0] = r0; bh[2*pj+1][0] = r1;
                bh[2*pj][1] = r2; bh[2*pj+1][1] = r3;
                LDSM_X4(r0, r1, r2, r3, addr + (OFF_BLO - OFF_BHI));
                bl[2*pj][0] = r0; bl[2*pj+1][0] = r1;
                bl[2*pj][1] = r2; bl[2*pj+1][1] = r3;
            }
            #pragma unroll
            for (int mi = 0; mi < 4; mi++)
                #pragma unroll
                for (int nj = 0; nj < 4; nj++) {
                    mma16816(acc[mi][nj], ah[mi], bh[nj][0], bh[nj][1]);
                    mma16816(acc[mi][nj], ah[mi], bl[nj][0], bl[nj][1]);
                    mma16816(acc[mi][nj], al[mi], bh[nj][0], bh[nj][1]);
                }
        }
        __syncthreads();
    }

    // ---------------- epilogue ----------------------------------------------
    const int mrow = lane >> 2;
    const int ncol = (lane & 3) * 2;

    #pragma unroll
    for (int mi = 0; mi < 4; mi++) {
        #pragma unroll
        for (int half = 0; half < 2; half++) {
            int t = t0 + wy*64 + mi*16 + mrow + half*8;
            #pragma unroll
            for (int nj = 0; nj < 4; nj++) {
                int f = f0 + wx*32 + nj*8 + ncol;
                float v0 = acc[mi][nj][half*2 + 0];
                float v1 = acc[mi][nj][half*2 + 1];
                if (mode == 0) {
                    int bidx = t >> 11, sidx = t & 2047;
                    int hh = f / 192;
                    int c = f - hh*192;
                    int kind = c >> 6, d = c & 63;
                    if (kind == 0) { v0 *= QSCALE; v1 *= QSCALE; }
                    __nv_bfloat16* hp = (kind == 0) ? g_qh : ((kind == 1) ? g_kh : g_vh);
                    __nv_bfloat16* lp = (kind == 0) ? g_ql : ((kind == 1) ? g_kl : g_vl);
                    size_t idx = (((size_t)(bidx*Hn + hh))*Sn + sidx)*HDn + d;
                    __nv_bfloat162 h2 = __floats2bfloat162_rn(v0, v1);
                    __nv_bfloat162 l2 = __floats2bfloat162_rn(
                        v0 - __bfloat162float(h2.x), v1 - __bfloat162float(h2.y));
                    *(__nv_bfloat162*)(hp + idx) = h2;
                    *(__nv_bfloat162*)(lp + idx) = l2;
                } else {
                    float2* p = (float2*)&outp[(size_t)t*En + f];
                    *p = make_float2(v0 + bias[f], v1 + bias[f + 1]);
                }
            }
        }
    }
}

// ---------------------------------------------------------------------------
// Kernel 2: causal flash attention, split-bf16 HMMA, FA2 register layout.
// Block: 128 q-rows (8 warps x m16), kv tiles of 64, double-buffered cp.async.
// qt remapped longest-first to kill the wave tail.
// ---------------------------------------------------------------------------
#define AROWB 144               // 64 bf16 = 128B data + 16B pad
#define A_QH 0
#define A_QL (128*AROWB)        // 18432
#define A_ST0 (2*128*AROWB)     // 36864
#define A_KH 0
#define A_KL (64*AROWB)         // 9216
#define A_VH (2*64*AROWB)       // 18432
#define A_VL (3*64*AROWB)       // 27648
#define A_STAGE (4*64*AROWB)    // 36864
#define ATTN_SMEM (A_ST0 + 2*A_STAGE)   // 110592

__global__ __launch_bounds__(256) void attn_mma_kernel()
{
    extern __shared__ char dsm[];
    const uint32_t sb = smem_u32(dsm);
    const int tid = threadIdx.x;
    const int wid = tid >> 5, lane = tid & 31;
    const int qt = gridDim.x - 1 - blockIdx.x;     // longest-first scheduling
    const int bh = blockIdx.y;
    const int q0 = qt * 128;
    const size_t gbase = (size_t)bh * Sn * HDn;
    const int nk = 2*qt + 2;

    #define LOAD_KV(kt_, s_) do {                                             \
        uint32_t st_ = sb + A_ST0 + (uint32_t)(s_)*A_STAGE;                   \
        int kv_ = (kt_)*64;                                                   \
        _Pragma("unroll")                                                     \
        for (int j_ = 0; j_ < 2; j_++) {                                      \
            int c_ = tid + j_*256;                                            \
            int row_ = c_ >> 3, ch_ = c_ & 7;                                 \
            uint32_t so_ = (uint32_t)(row_*AROWB + ch_*16);                   \
            size_t go_ = gbase + (size_t)(kv_ + row_)*HDn + ch_*8;            \
            ldgsts16(st_ + A_KH + so_, g_kh + go_);                           \
            ldgsts16(st_ + A_KL + so_, g_kl + go_);                           \
            ldgsts16(st_ + A_VH + so_, g_vh + go_);                           \
            ldgsts16(st_ + A_VL + so_, g_vl + go_);                           \
        } } while (0)

    // Q tile (hi/lo) -> smem
    #pragma unroll
    for (int j = 0; j < 4; j++) {
        int c = tid + j*256;
        int row = c >> 3, ch = c & 7;
        uint32_t so = (uint32_t)(row*AROWB + ch*16);
        size_t go = gbase + (size_t)(q0 + row)*HDn + ch*8;
        ldgsts16(sb + A_QH + so, g_qh + go);
        ldgsts16(sb + A_QL + so, g_ql + go);
    }
    asm volatile("cp.async.commit_group;");
    LOAD_KV(0, 0);
    asm volatile("cp.async.commit_group;");
    if (nk > 1) LOAD_KV(1, 1);
    asm volatile("cp.async.commit_group;");

    asm volatile("cp.async.wait_group 2;");   // Q ready
    __syncthreads();

    // Q fragments (persist in registers)
    uint32_t qh_[4][4], ql_[4][4];
    {
        uint32_t r_ = (uint32_t)(wid*16 + (lane & 15));
        uint32_t cb = (uint32_t)((lane >> 4) << 4);
        #pragma unroll
        for (int kk = 0; kk < 4; kk++) {
            uint32_t addr = sb + A_QH + r_*AROWB + (uint32_t)kk*32 + cb;
            LDSM_X4(qh_[kk][0], qh_[kk][1], qh_[kk][2], qh_[kk][3], addr);
            LDSM_X4(ql_[kk][0], ql_[kk][1], ql_[kk][2], ql_[kk][3], addr + (A_QL - A_QH));
        }
    }

    float m0 = -INFINITY, m1 = -INFINITY, l0 = 0.f, l1 = 0.f;
    float acc[8][4] = {};

    for (int kt = 0; kt < nk; kt++) {
        asm volatile("cp.async.wait_group 1;");
        __syncthreads();

        const uint32_t st = sb + A_ST0 + (uint32_t)(kt & 1)*A_STAGE;
        const int kv0 = kt * 64;

        // ---- S = Q @ K^T (3-term split) ----
        float s[8][4] = {};
        {
            uint32_t r_ = (uint32_t)(lane & 15);
            uint32_t cb = (uint32_t)((lane >> 4) << 4);
            #pragma unroll
            for (int kk = 0; kk < 4; kk++) {
                uint32_t kh[8][2], kl[8][2];
                #pragma unroll
                for (int pj = 0; pj < 4; pj++) {
                    uint32_t addr = st + A_KH + (uint32_t)(pj*16 + r_)*AROWB
                                  + (uint32_t)kk*32 + cb;
                    uint32_t r0, r1, r2, r3;
                    LDSM_X4(r0, r1, r2, r3, addr);
                    kh[2*pj][0]=r0; kh[2*pj][1]=r2; kh[2*pj+1][0]=r1; kh[2*pj+1][1]=r3;
                    LDSM_X4(r0, r1, r2, r3, addr + (A_KL - A_KH));
                    kl[2*pj][0]=r0; kl[2*pj][1]=r2; kl[2*pj+1][0]=r1; kl[2*pj+1][1]=r3;
                }
                #pragma unroll
                for (int nj = 0; nj < 8; nj++) {
                    mma16816(s[nj], qh_[kk], kh[nj][0], kh[nj][1]);
                    mma16816(s[nj], qh_[kk], kl[nj][0], kl[nj][1]);
                    mma16816(s[nj], ql_[kk], kh[nj][0], kh[nj][1]);
                }
            }
        }

        // ---- causal mask ----
        const int rbase = q0 + wid*16 + (lane >> 2);
        if (kv0 + 63 > q0 + wid*16) {
            #pragma unroll
            for (int nj = 0; nj < 8; nj++)
                #pragma unroll
                for (int i = 0; i < 4; i++) {
                    int col = kv0 + nj*8 + (lane & 3)*2 + (i & 1);
                    int row = rbase + (i >> 1)*8;
                    if (col > row) s[nj][i] = -INFINITY;
                }
        }

        // ---- online softmax (exp2 domain) ----
        float mx0 = -INFINITY, mx1 = -INFINITY;
        #pragma unroll
        for (int nj = 0; nj < 8; nj++) {
            mx0 = fmaxf(mx0, fmaxf(s[nj][0], s[nj][1]));
            mx1 = fmaxf(mx1, fmaxf(s[nj][2], s[nj][3]));
        }
        mx0 = fmaxf(mx0, __shfl_xor_sync(0xffffffffu, mx0, 1));
        mx0 = fmaxf(mx0, __shfl_xor_sync(0xffffffffu, mx0, 2));
        mx1 = fmaxf(mx1, __shfl_xor_sync(0xffffffffu, mx1, 1));
        mx1 = fmaxf(mx1, __shfl_xor_sync(0xffffffffu, mx1, 2));
        float mn0 = fmaxf(m0, mx0), mn1 = fmaxf(m1, mx1);
        float al0 = ex2f(m0 - mn0), al1 = ex2f(m1 - mn1);
        m0 = mn0; m1 = mn1;
        float rs0 = 0.f, rs1 = 0.f;
        #pragma unroll
        for (int nj = 0; nj < 8; nj++) {
            float p0 = ex2f(s[nj][0] - mn0), p1 = ex2f(s[nj][1] - mn0);
            float p2 = ex2f(s[nj][2] - mn1), p3 = ex2f(s[nj][3] - mn1);
            s[nj][0] = p0; s[nj][1] = p1; s[nj][2] = p2; s[nj][3] = p3;
            rs0 += p0 + p1; rs1 += p2 + p3;
        }
        rs0 += __shfl_xor_sync(0xffffffffu, rs0, 1);
        rs0 += __shfl_xor_sync(0xffffffffu, rs0, 2);
        rs1 += __shfl_xor_sync(0xffffffffu, rs1, 1);
        rs1 += __shfl_xor_sync(0xffffffffu, rs1, 2);
        l0 = l0*al0 + rs0;
        l1 = l1*al1 + rs1;
        #pragma unroll
        for (int nj = 0; nj < 8; nj++) {
            acc[nj][0] *= al0; acc[nj][1] *= al0;
            acc[nj][2] *= al1; acc[nj][3] *= al1;
        }

        // ---- O += P @ V (3-term split; V frags via ldmatrix.trans) ----
        {
            uint32_t rr = (uint32_t)(((lane >> 4) << 3) + (lane & 7));
            uint32_t cb = (uint32_t)(((lane >> 3) & 1) << 4);
            #pragma unroll
            for (int kk2 = 0; kk2 < 4; kk2++) {
                uint32_t pah[4], pal[4];
                #pragma unroll
                for (int tp = 0; tp < 2; tp++) {
                    int t_ = 2*kk2 + tp;
                    float p0 = s[t_][0], p1 = s[t_][1], p2 = s[t_][2], p3 = s[t_][3];
                    __nv_bfloat162 h01 = __floats2bfloat162_rn(p0, p1);
                    __nv_bfloat162 h23 = __floats2bfloat162_rn(p2, p3);
                    pah[2*tp+0] = *reinterpret_cast<uint32_t*>(&h01);
                    pah[2*tp+1] = *reinterpret_cast<uint32_t*>(&h23);
                    pal[2*tp+0] = pack_bf2(p0 - __bfloat162float(h01.x),
                                           p1 - __bfloat162float(h01.y));
                    pal[2*tp+1] = pack_bf2(p2 - __bfloat162float(h23.x),
                                           p3 - __bfloat162float(h23.y));
                }
                uint32_t bvh[8][2], bvl[8][2];
                #pragma unroll
                for (int dj = 0; dj < 4; dj++) {
                    uint32_t addr = st + A_VH + (uint32_t)(kk2*16 + rr)*AROWB
                                  + (uint32_t)dj*32 + cb;
                    uint32_t r0, r1, r2, r3;
                    LDSM_X4_T(r0, r1, r2, r3, addr);
                    bvh[2*dj][0]=r0; bvh[2*dj][1]=r2; bvh[2*dj+1][0]=r1; bvh[2*dj+1][1]=r3;
                    LDSM_X4_T(r0, r1, r2, r3, addr + (A_VL - A_VH));
                    bvl[2*dj][0]=r0; bvl[2*dj][1]=r2; bvl[2*dj+1][0]=r1; bvl[2*dj+1][1]=r3;
                }
                #pragma unroll
                for (int nj = 0; nj < 8; nj++) {
                    mma16816(acc[nj], pah, bvh[nj][0], bvh[nj][1]);
                    mma16816(acc[nj], pah, bvl[nj][0], bvl[nj][1]);
                    mma16816(acc[nj], pal, bvh[nj][0], bvh[nj][1]);
                }
            }
        }

        __syncthreads();
        if (kt + 2 < nk) LOAD_KV(kt + 2, kt & 1);
        asm volatile("cp.async.commit_group;");
    }

    // ---- epilogue: normalize, write bf16 hi/lo for proj GEMM ----
    float inv0 = 1.f / l0, inv1 = 1.f / l1;
    const int b = bh >> 4, h = bh & 15;
    const int r0_ = q0 + wid*16 + (lane >> 2);
    #pragma unroll
    for (int nj = 0; nj < 8; nj++) {
        int d = nj*8 + (lane & 3)*2;
        size_t i0 = (size_t)(b*Sn + r0_)*En + h*HDn + d;
        size_t i1 = i0 + (size_t)8*En;
        float o0 = acc[nj][0]*inv0, o1 = acc[nj][1]*inv0;
        float o2 = acc[nj][2]*inv1, o3 = acc[nj][3]*inv1;
        __nv_bfloat162 h01 = __floats2bfloat162_rn(o0, o1);
        __nv_bfloat162 l01 = __floats2bfloat162_rn(o0 - __bfloat162float(h01.x),
                                                   o1 - __bfloat162float(h01.y));
        __nv_bfloat162 h23 = __floats2bfloat162_rn(o2, o3);
        __nv_bfloat162 l23 = __floats2bfloat162_rn(o2 - __bfloat162float(h23.x),
                                                   o3 - __bfloat162float(h23.y));
        *(__nv_bfloat162*)(g_att_hi + i0) = h01;
        *(__nv_bfloat162*)(g_att_lo + i0) = l01;
        *(__nv_bfloat162*)(g_att_hi + i1) = h23;
        *(__nv_bfloat162*)(g_att_lo + i1) = l23;
    }
}

// ---------------------------------------------------------------------------
extern "C" void kernel_launch(void* const* d_in, const int* in_sizes, int n_in,
                              void* d_out, int out_size)
{
    const float* x      = (const float*)d_in[0];
    const float* w_qkv  = (const float*)d_in[1];
    const float* w_proj = (const float*)d_in[2];
    const float* b_proj = (const float*)d_in[3];
    float* out = (float*)d_out;

    cudaFuncSetAttribute(gemm_split_kernel,
                         cudaFuncAttributeMaxDynamicSharedMemorySize, GEMM_SMEM);
    cudaFuncSetAttribute(attn_mma_kernel,
                         cudaFuncAttributeMaxDynamicSharedMemorySize, ATTN_SMEM);

    __nv_bfloat16 *xhi, *xlo, *wqhi, *wqlo, *wphi, *wplo, *athi, *atlo;
    cudaGetSymbolAddress((void**)&xhi,  g_x_hi);
    cudaGetSymbolAddress((void**)&xlo,  g_x_lo);
    cudaGetSymbolAddress((void**)&wqhi, g_wq_hi);
    cudaGetSymbolAddress((void**)&wqlo, g_wq_lo);
    cudaGetSymbolAddress((void**)&wphi, g_wp_hi);
    cudaGetSymbolAddress((void**)&wplo, g_wp_lo);
    cudaGetSymbolAddress((void**)&athi, g_att_hi);
    cudaGetSymbolAddress((void**)&atlo, g_att_lo);

    // fp32 -> bf16 hi/lo splits
    split_kernel<<<(Tn*En/4 + 255)/256, 256>>>((const float4*)x,
        (__nv_bfloat162*)xhi, (__nv_bfloat162*)xlo, Tn*En/4);
    split_kernel<<<(F1n*En/4 + 255)/256, 256>>>((const float4*)w_qkv,
        (__nv_bfloat162*)wqhi, (__nv_bfloat162*)wqlo, F1n*En/4);
    split_kernel<<<(En*En/4 + 255)/256, 256>>>((const float4*)w_proj,
        (__nv_bfloat162*)wphi, (__nv_bfloat162*)wplo, En*En/4);

    // QKV GEMM (split-bf16 HMMA) -> bf16 hi/lo Q/K/V (Q pre-scaled)
    gemm_split_kernel<<<dim3(F1n/BNn, Tn/BMm), 256, GEMM_SMEM>>>(
        xhi, xlo, wqhi, wqlo, nullptr, nullptr, 0);

    // causal flash attention (split-bf16 HMMA)
    attn_mma_kernel<<<dim3(Sn/128, Bn*Hn), 256, ATTN_SMEM>>>();

    // output projection (split-bf16 HMMA) + bias
    gemm_split_kernel<<<dim3(En/BNn, Tn/BMm), 256, GEMM_SMEM>>>(
        athi, atlo, wphi, wplo, out, b_proj, 1);
}

// round 7
// speedup vs baseline: 2.8805x; 1.0742x over previous
#include <cuda_runtime.h>
#include <cuda_bf16.h>
#include <math.h>
#include <stdint.h>

#define Bn 4
#define Sn 2048
#define En 1024
#define Hn 16
#define HDn 64
#define Tn (Bn*Sn)        // 8192 tokens
#define F1n (3*En)        // 3072

#define QSCALE 0.180336880436f   // 0.125 * log2(e): scores land in exp2 domain

// ---------------------------------------------------------------------------
// Scratch (static device globals — allocation-free per harness rules)
// ---------------------------------------------------------------------------
__device__ __nv_bfloat16 g_qh[(size_t)Bn*Hn*Sn*HDn];  // [b*H+h][s][d] (scaled)
__device__ __nv_bfloat16 g_ql[(size_t)Bn*Hn*Sn*HDn];
__device__ __nv_bfloat16 g_kh[(size_t)Bn*Hn*Sn*HDn];
__device__ __nv_bfloat16 g_kl[(size_t)Bn*Hn*Sn*HDn];
__device__ __nv_bfloat16 g_vh[(size_t)Bn*Hn*Sn*HDn];
__device__ __nv_bfloat16 g_vl[(size_t)Bn*Hn*Sn*HDn];
__device__ __nv_bfloat16 g_x_hi[(size_t)Tn*En];
__device__ __nv_bfloat16 g_x_lo[(size_t)Tn*En];
__device__ __nv_bfloat16 g_wq_hi[(size_t)F1n*En];
__device__ __nv_bfloat16 g_wq_lo[(size_t)F1n*En];
__device__ __nv_bfloat16 g_wp_hi[(size_t)En*En];
__device__ __nv_bfloat16 g_wp_lo[(size_t)En*En];
__device__ __nv_bfloat16 g_att_hi[(size_t)Tn*En];
__device__ __nv_bfloat16 g_att_lo[(size_t)Tn*En];

// ---------------------------------------------------------------------------
// Helpers (baseline PTX only — no 'a'-suffix arch features)
// ---------------------------------------------------------------------------
__device__ __forceinline__ uint32_t smem_u32(const void* p) {
    uint32_t a;
    asm("{ .reg .u64 t; cvta.to.shared.u64 t, %1; cvt.u32.u64 %0, t; }" : "=r"(a) : "l"(p));
    return a;
}

__device__ __forceinline__ void ldgsts16(uint32_t dst, const void* src) {
    asm volatile("cp.async.cg.shared.global [%0], [%1], 16;" :: "r"(dst), "l"(src));
}

#define LDSM_X4(r0, r1, r2, r3, addr) \
    asm volatile("ldmatrix.sync.aligned.m8n8.x4.shared.b16 {%0,%1,%2,%3}, [%4];" \
        : "=r"(r0), "=r"(r1), "=r"(r2), "=r"(r3) : "r"(addr))

#define LDSM_X4_T(r0, r1, r2, r3, addr) \
    asm volatile("ldmatrix.sync.aligned.m8n8.x4.trans.shared.b16 {%0,%1,%2,%3}, [%4];" \
        : "=r"(r0), "=r"(r1), "=r"(r2), "=r"(r3) : "r"(addr))

__device__ __forceinline__ void mma16816(float c[4], const uint32_t a[4],
                                         uint32_t b0, uint32_t b1) {
    asm volatile(
        "mma.sync.aligned.m16n8k16.row.col.f32.bf16.bf16.f32 "
        "{%0,%1,%2,%3}, {%4,%5,%6,%7}, {%8,%9}, {%0,%1,%2,%3};"
        : "+f"(c[0]), "+f"(c[1]), "+f"(c[2]), "+f"(c[3])
        : "r"(a[0]), "r"(a[1]), "r"(a[2]), "r"(a[3]), "r"(b0), "r"(b1));
}

__device__ __forceinline__ float ex2f(float x) {
    float r; asm("ex2.approx.ftz.f32 %0, %1;" : "=f"(r) : "f"(x)); return r;
}

__device__ __forceinline__ uint32_t pack_bf2(float a, float b) {
    __nv_bfloat162 h = __floats2bfloat162_rn(a, b);
    return *reinterpret_cast<uint32_t*>(&h);
}

// GEMM smem swizzle: 64B rows, chunk XOR — 16B aligned, ldmatrix conflict-free
__device__ __forceinline__ uint32_t gsw(uint32_t row, uint32_t coloff) {
    return row*64u + (coloff ^ (((row >> 1) & 3u) << 4));
}

// ---------------------------------------------------------------------------
// Kernel 0: fp32 -> (bf16 hi, bf16 lo) split, float4-vectorized
// ---------------------------------------------------------------------------
__global__ __launch_bounds__(256) void split_kernel(
    const float4* __restrict__ src, __nv_bfloat162* __restrict__ hi,
    __nv_bfloat162* __restrict__ lo, int n4)
{
    int i = blockIdx.x * 256 + threadIdx.x;
    if (i >= n4) return;
    float4 v = src[i];
    __nv_bfloat16 h0 = __float2bfloat16(v.x), h1 = __float2bfloat16(v.y);
    __nv_bfloat16 h2 = __float2bfloat16(v.z), h3 = __float2bfloat16(v.w);
    __nv_bfloat162 a; a.x = h0; a.y = h1;
    __nv_bfloat162 b; b.x = h2; b.y = h3;
    __nv_bfloat162 c; c.x = __float2bfloat16(v.x - __bfloat162float(h0));
    c.y = __float2bfloat16(v.y - __bfloat162float(h1));
    __nv_bfloat162 d; d.x = __float2bfloat16(v.z - __bfloat162float(h2));
    d.y = __float2bfloat16(v.w - __bfloat162float(h3));
    hi[2*i] = a; hi[2*i+1] = b;
    lo[2*i] = c; lo[2*i+1] = d;
}

// ---------------------------------------------------------------------------
// Split-bf16 HMMA GEMM.  C[r][f] = sum_k A[r][k]*B[f][k]   (K = 1024)
// BM=128, BN=128, BK=32. 8 warps (2x4), each a 64x32 tile.
// 3-stage cp.async ring (swizzled 64B rows), ONE __syncthreads per iteration,
// 2 CTAs/SM (3*32KB = 96KB/CTA).
//   mode 0: split C into bf16 hi/lo head-major q/k/v (q pre-scaled)
//   mode 1: C + bias -> out (fp32, row-major)
// ---------------------------------------------------------------------------
#define BMm 128
#define BNn 128
#define BKk 32
#define NKI (En/BKk)            // 32
#define OFF_ALO  8192           // 128*64
#define OFF_BHI 16384
#define OFF_BLO 24576
#define STAGEB  32768
#define GEMM_SMEM (3*STAGEB)    // 98304 (2 CTAs/SM = 196KB)

__global__ __launch_bounds__(256, 2) void gemm_split_kernel(
    const __nv_bfloat16* __restrict__ Ahi, const __nv_bfloat16* __restrict__ Alo,
    const __nv_bfloat16* __restrict__ Bhi, const __nv_bfloat16* __restrict__ Blo,
    float* __restrict__ outp, const float* __restrict__ bias, int mode)
{
    extern __shared__ char dsm[];
    const uint32_t sb = smem_u32(dsm);
    const int tid = threadIdx.x;
    const int wid = tid >> 5, lane = tid & 31;
    const int wy = wid & 1, wx = wid >> 1;         // warp tile: (wy*64, wx*32)
    const int t0 = blockIdx.y * BMm, f0 = blockIdx.x * BNn;

    #define LOAD_STAGE(ki, s) do {                                            \
        uint32_t base_ = sb + (uint32_t)(s)*STAGEB;                           \
        int kofs_ = (ki)*BKk;                                                 \
        _Pragma("unroll")                                                     \
        for (int jj = 0; jj < 2; jj++) {                                      \
            int c_ = tid + jj*256;                                            \
            uint32_t row_ = (uint32_t)(c_ >> 2), ch_ = (uint32_t)(c_ & 3);    \
            uint32_t so_ = gsw(row_, ch_*16u);                                \
            size_t ga_ = (size_t)(t0 + (int)row_)*En + kofs_ + (int)ch_*8;    \
            size_t gb_ = (size_t)(f0 + (int)row_)*En + kofs_ + (int)ch_*8;    \
            ldgsts16(base_ + so_,           Ahi + ga_);                       \
            ldgsts16(base_ + OFF_ALO + so_, Alo + ga_);                       \
            ldgsts16(base_ + OFF_BHI + so_, Bhi + gb_);                       \
            ldgsts16(base_ + OFF_BLO + so_, Blo + gb_);                       \
        }                                                                     \
    } while (0)

    float acc[4][4][4] = {};   // [mi][nj][frag]

    LOAD_STAGE(0, 0);
    asm volatile("cp.async.commit_group;");
    LOAD_STAGE(1, 1);
    asm volatile("cp.async.commit_group;");

    int slot = 0;
    for (int i = 0; i < NKI; i++) {
        asm volatile("cp.async.wait_group 1;");   // stage i resident
        __syncthreads();                          // also fences slot reuse

        if (i + 2 < NKI) {
            int ls = slot + 2; if (ls >= 3) ls -= 3;
            LOAD_STAGE(i + 2, ls);
        }
        asm volatile("cp.async.commit_group;");

        const uint32_t base = sb + (uint32_t)slot*STAGEB;
        const uint32_t lrow = lane & 15;
        const uint32_t lcol = (lane >> 4) << 4;

        #pragma unroll
        for (int kk = 0; kk < 2; kk++) {
            const uint32_t coff = (uint32_t)kk*32 + lcol;
            uint32_t ah[4][4], al[4][4];
            #pragma unroll
            for (int mi = 0; mi < 4; mi++) {
                uint32_t r = (uint32_t)(wy*64 + mi*16) + lrow;
                uint32_t addr = base + gsw(r, coff);
                LDSM_X4(ah[mi][0], ah[mi][1], ah[mi][2], ah[mi][3], addr);
                LDSM_X4(al[mi][0], al[mi][1], al[mi][2], al[mi][3], addr + OFF_ALO);
            }
            uint32_t bh[4][2], bl[4][2];
            #pragma unroll
            for (int pj = 0; pj < 2; pj++) {
                uint32_t r = (uint32_t)(wx*32 + pj*16) + lrow;
                uint32_t addr = base + OFF_BHI + gsw(r, coff);
                uint32_t r0, r1, r2, r3;
                LDSM_X4(r0, r1, r2, r3, addr);
                bh[2*pj][0] = r0; bh[2*pj+1][0] = r1;
                bh[2*pj][1] = r2; bh[2*pj+1][1] = r3;
                LDSM_X4(r0, r1, r2, r3, addr + (OFF_BLO - OFF_BHI));
                bl[2*pj][0] = r0; bl[2*pj+1][0] = r1;
                bl[2*pj][1] = r2; bl[2*pj+1][1] = r3;
            }
            #pragma unroll
            for (int mi = 0; mi < 4; mi++)
                #pragma unroll
                for (int nj = 0; nj < 4; nj++) {
                    mma16816(acc[mi][nj], ah[mi], bh[nj][0], bh[nj][1]);
                    mma16816(acc[mi][nj], ah[mi], bl[nj][0], bl[nj][1]);
                    mma16816(acc[mi][nj], al[mi], bh[nj][0], bh[nj][1]);
                }
        }
        if (++slot == 3) slot = 0;
    }

    // ---------------- epilogue ----------------------------------------------
    const int mrow = lane >> 2;
    const int ncol = (lane & 3) * 2;

    #pragma unroll
    for (int mi = 0; mi < 4; mi++) {
        #pragma unroll
        for (int half = 0; half < 2; half++) {
            int t = t0 + wy*64 + mi*16 + mrow + half*8;
            #pragma unroll
            for (int nj = 0; nj < 4; nj++) {
                int f = f0 + wx*32 + nj*8 + ncol;
                float v0 = acc[mi][nj][half*2 + 0];
                float v1 = acc[mi][nj][half*2 + 1];
                if (mode == 0) {
                    int bidx = t >> 11, sidx = t & 2047;
                    int hh = f / 192;
                    int c = f - hh*192;
                    int kind = c >> 6, d = c & 63;
                    if (kind == 0) { v0 *= QSCALE; v1 *= QSCALE; }
                    __nv_bfloat16* hp = (kind == 0) ? g_qh : ((kind == 1) ? g_kh : g_vh);
                    __nv_bfloat16* lp = (kind == 0) ? g_ql : ((kind == 1) ? g_kl : g_vl);
                    size_t idx = (((size_t)(bidx*Hn + hh))*Sn + sidx)*HDn + d;
                    __nv_bfloat162 h2 = __floats2bfloat162_rn(v0, v1);
                    __nv_bfloat162 l2 = __floats2bfloat162_rn(
                        v0 - __bfloat162float(h2.x), v1 - __bfloat162float(h2.y));
                    *(__nv_bfloat162*)(hp + idx) = h2;
                    *(__nv_bfloat162*)(lp + idx) = l2;
                } else {
                    float2* p = (float2*)&outp[(size_t)t*En + f];
                    *p = make_float2(v0 + bias[f], v1 + bias[f + 1]);
                }
            }
        }
    }
}

// ---------------------------------------------------------------------------
// Kernel 2: causal flash attention, split-bf16 HMMA, FA2 register layout.
// Block: 128 q-rows (8 warps x m16), kv tiles of 64, 3-stage cp.async ring,
// ONE __syncthreads per kv-tile. qt remapped longest-first.
// ---------------------------------------------------------------------------
#define AROWB 144               // 64 bf16 = 128B data + 16B pad (16B-aligned)
#define A_QH 0
#define A_QL (128*AROWB)        // 18432
#define A_ST0 (2*128*AROWB)     // 36864
#define A_KH 0
#define A_KL (64*AROWB)         // 9216
#define A_VH (2*64*AROWB)       // 18432
#define A_VL (3*64*AROWB)       // 27648
#define A_STAGE (4*64*AROWB)    // 36864
#define ATTN_SMEM (A_ST0 + 3*A_STAGE)   // 147456

__global__ __launch_bounds__(256) void attn_mma_kernel()
{
    extern __shared__ char dsm[];
    const uint32_t sb = smem_u32(dsm);
    const int tid = threadIdx.x;
    const int wid = tid >> 5, lane = tid & 31;
    const int qt = gridDim.x - 1 - blockIdx.x;     // longest-first scheduling
    const int bh = blockIdx.y;
    const int q0 = qt * 128;
    const size_t gbase = (size_t)bh * Sn * HDn;
    const int nk = 2*qt + 2;                       // nk >= 2 always

    #define LOAD_KV(kt_, s_) do {                                             \
        uint32_t st_ = sb + A_ST0 + (uint32_t)(s_)*A_STAGE;                   \
        int kv_ = (kt_)*64;                                                   \
        _Pragma("unroll")                                                     \
        for (int j_ = 0; j_ < 2; j_++) {                                      \
            int c_ = tid + j_*256;                                            \
            int row_ = c_ >> 3, ch_ = c_ & 7;                                 \
            uint32_t so_ = (uint32_t)(row_*AROWB + ch_*16);                   \
            size_t go_ = gbase + (size_t)(kv_ + row_)*HDn + ch_*8;            \
            ldgsts16(st_ + A_KH + so_, g_kh + go_);                           \
            ldgsts16(st_ + A_KL + so_, g_kl + go_);                           \
            ldgsts16(st_ + A_VH + so_, g_vh + go_);                           \
            ldgsts16(st_ + A_VL + so_, g_vl + go_);                           \
        } } while (0)

    // Q tile (hi/lo) -> smem
    #pragma unroll
    for (int j = 0; j < 4; j++) {
        int c = tid + j*256;
        int row = c >> 3, ch = c & 7;
        uint32_t so = (uint32_t)(row*AROWB + ch*16);
        size_t go = gbase + (size_t)(q0 + row)*HDn + ch*8;
        ldgsts16(sb + A_QH + so, g_qh + go);
        ldgsts16(sb + A_QL + so, g_ql + go);
    }
    asm volatile("cp.async.commit_group;");
    LOAD_KV(0, 0);
    asm volatile("cp.async.commit_group;");
    LOAD_KV(1, 1);
    asm volatile("cp.async.commit_group;");

    asm volatile("cp.async.wait_group 2;");   // Q resident
    __syncthreads();

    // Q fragments (persist in registers)
    uint32_t qh_[4][4], ql_[4][4];
    {
        uint32_t r_ = (uint32_t)(wid*16 + (lane & 15));
        uint32_t cb = (uint32_t)((lane >> 4) << 4);
        #pragma unroll
        for (int kk = 0; kk < 4; kk++) {
            uint32_t addr = sb + A_QH + r_*AROWB + (uint32_t)kk*32 + cb;
            LDSM_X4(qh_[kk][0], qh_[kk][1], qh_[kk][2], qh_[kk][3], addr);
            LDSM_X4(ql_[kk][0], ql_[kk][1], ql_[kk][2], ql_[kk][3], addr + (A_QL - A_QH));
        }
    }

    float m0 = -INFINITY, m1 = -INFINITY, l0 = 0.f, l1 = 0.f;
    float acc[8][4] = {};

    int slot = 0;
    for (int kt = 0; kt < nk; kt++) {
        asm volatile("cp.async.wait_group 1;");   // KV_kt resident
        __syncthreads();                          // fences slot reuse

        if (kt + 2 < nk) {
            int ls = slot + 2; if (ls >= 3) ls -= 3;
            LOAD_KV(kt + 2, ls);
        }
        asm volatile("cp.async.commit_group;");

        const uint32_t st = sb + A_ST0 + (uint32_t)slot*A_STAGE;
        const int kv0 = kt * 64;

        // ---- S = Q @ K^T (3-term split) ----
        float s[8][4] = {};
        {
            uint32_t r_ = (uint32_t)(lane & 15);
            uint32_t cb = (uint32_t)((lane >> 4) << 4);
            #pragma unroll
            for (int kk = 0; kk < 4; kk++) {
                uint32_t kh[8][2], kl[8][2];
                #pragma unroll
                for (int pj = 0; pj < 4; pj++) {
                    uint32_t addr = st + A_KH + (uint32_t)(pj*16 + r_)*AROWB
                                  + (uint32_t)kk*32 + cb;
                    uint32_t r0, r1, r2, r3;
                    LDSM_X4(r0, r1, r2, r3, addr);
                    kh[2*pj][0]=r0; kh[2*pj][1]=r2; kh[2*pj+1][0]=r1; kh[2*pj+1][1]=r3;
                    LDSM_X4(r0, r1, r2, r3, addr + (A_KL - A_KH));
                    kl[2*pj][0]=r0; kl[2*pj][1]=r2; kl[2*pj+1][0]=r1; kl[2*pj+1][1]=r3;
                }
                #pragma unroll
                for (int nj = 0; nj < 8; nj++) {
                    mma16816(s[nj], qh_[kk], kh[nj][0], kh[nj][1]);
                    mma16816(s[nj], qh_[kk], kl[nj][0], kl[nj][1]);
                    mma16816(s[nj], ql_[kk], kh[nj][0], kh[nj][1]);
                }
            }
        }

        // ---- causal mask ----
        const int rbase = q0 + wid*16 + (lane >> 2);
        if (kv0 + 63 > q0 + wid*16) {
            #pragma unroll
            for (int nj = 0; nj < 8; nj++)
                #pragma unroll
                for (int i = 0; i < 4; i++) {
                    int col = kv0 + nj*8 + (lane & 3)*2 + (i & 1);
                    int row = rbase + (i >> 1)*8;
                    if (col > row) s[nj][i] = -INFINITY;
                }
        }

        // ---- online softmax (exp2 domain) ----
        float mx0 = -INFINITY, mx1 = -INFINITY;
        #pragma unroll
        for (int nj = 0; nj < 8; nj++) {
            mx0 = fmaxf(mx0, fmaxf(s[nj][0], s[nj][1]));
            mx1 = fmaxf(mx1, fmaxf(s[nj][2], s[nj][3]));
        }
        mx0 = fmaxf(mx0, __shfl_xor_sync(0xffffffffu, mx0, 1));
        mx0 = fmaxf(mx0, __shfl_xor_sync(0xffffffffu, mx0, 2));
        mx1 = fmaxf(mx1, __shfl_xor_sync(0xffffffffu, mx1, 1));
        mx1 = fmaxf(mx1, __shfl_xor_sync(0xffffffffu, mx1, 2));
        float mn0 = fmaxf(m0, mx0), mn1 = fmaxf(m1, mx1);
        float al0 = ex2f(m0 - mn0), al1 = ex2f(m1 - mn1);
        m0 = mn0; m1 = mn1;
        float rs0 = 0.f, rs1 = 0.f;
        #pragma unroll
        for (int nj = 0; nj < 8; nj++) {
            float p0 = ex2f(s[nj][0] - mn0), p1 = ex2f(s[nj][1] - mn0);
            float p2 = ex2f(s[nj][2] - mn1), p3 = ex2f(s[nj][3] - mn1);
            s[nj][0] = p0; s[nj][1] = p1; s[nj][2] = p2; s[nj][3] = p3;
            rs0 += p0 + p1; rs1 += p2 + p3;
        }
        rs0 += __shfl_xor_sync(0xffffffffu, rs0, 1);
        rs0 += __shfl_xor_sync(0xffffffffu, rs0, 2);
        rs1 += __shfl_xor_sync(0xffffffffu, rs1, 1);
        rs1 += __shfl_xor_sync(0xffffffffu, rs1, 2);
        l0 = l0*al0 + rs0;
        l1 = l1*al1 + rs1;
        #pragma unroll
        for (int nj = 0; nj < 8; nj++) {
            acc[nj][0] *= al0; acc[nj][1] *= al0;
            acc[nj][2] *= al1; acc[nj][3] *= al1;
        }

        // ---- O += P @ V (3-term split; V frags via ldmatrix.trans) ----
        {
            uint32_t rr = (uint32_t)(((lane >> 4) << 3) + (lane & 7));
            uint32_t cb = (uint32_t)(((lane >> 3) & 1) << 4);
            #pragma unroll
            for (int kk2 = 0; kk2 < 4; kk2++) {
                uint32_t pah[4], pal[4];
                #pragma unroll
                for (int tp = 0; tp < 2; tp++) {
                    int t_ = 2*kk2 + tp;
                    float p0 = s[t_][0], p1 = s[t_][1], p2 = s[t_][2], p3 = s[t_][3];
                    __nv_bfloat162 h01 = __floats2bfloat162_rn(p0, p1);
                    __nv_bfloat162 h23 = __floats2bfloat162_rn(p2, p3);
                    pah[2*tp+0] = *reinterpret_cast<uint32_t*>(&h01);
                    pah[2*tp+1] = *reinterpret_cast<uint32_t*>(&h23);
                    pal[2*tp+0] = pack_bf2(p0 - __bfloat162float(h01.x),
                                           p1 - __bfloat162float(h01.y));
                    pal[2*tp+1] = pack_bf2(p2 - __bfloat162float(h23.x),
                                           p3 - __bfloat162float(h23.y));
                }
                uint32_t bvh[8][2], bvl[8][2];
                #pragma unroll
                for (int dj = 0; dj < 4; dj++) {
                    uint32_t addr = st + A_VH + (uint32_t)(kk2*16 + rr)*AROWB
                                  + (uint32_t)dj*32 + cb;
                    uint32_t r0, r1, r2, r3;
                    LDSM_X4_T(r0, r1, r2, r3, addr);
                    bvh[2*dj][0]=r0; bvh[2*dj][1]=r2; bvh[2*dj+1][0]=r1; bvh[2*dj+1][1]=r3;
                    LDSM_X4_T(r0, r1, r2, r3, addr + (A_VL - A_VH));
                    bvl[2*dj][0]=r0; bvl[2*dj][1]=r2; bvl[2*dj+1][0]=r1; bvl[2*dj+1][1]=r3;
                }
                #pragma unroll
                for (int nj = 0; nj < 8; nj++) {
                    mma16816(acc[nj], pah, bvh[nj][0], bvh[nj][1]);
                    mma16816(acc[nj], pah, bvl[nj][0], bvl[nj][1]);
                    mma16816(acc[nj], pal, bvh[nj][0], bvh[nj][1]);
                }
            }
        }

        if (++slot == 3) slot = 0;
    }

    // ---- epilogue: normalize, write bf16 hi/lo for proj GEMM ----
    float inv0 = 1.f / l0, inv1 = 1.f / l1;
    const int b = bh >> 4, h = bh & 15;
    const int r0_ = q0 + wid*16 + (lane >> 2);
    #pragma unroll
    for (int nj = 0; nj < 8; nj++) {
        int d = nj*8 + (lane & 3)*2;
        size_t i0 = (size_t)(b*Sn + r0_)*En + h*HDn + d;
        size_t i1 = i0 + (size_t)8*En;
        float o0 = acc[nj][0]*inv0, o1 = acc[nj][1]*inv0;
        float o2 = acc[nj][2]*inv1, o3 = acc[nj][3]*inv1;
        __nv_bfloat162 h01 = __floats2bfloat162_rn(o0, o1);
        __nv_bfloat162 l01 = __floats2bfloat162_rn(o0 - __bfloat162float(h01.x),
                                                   o1 - __bfloat162float(h01.y));
        __nv_bfloat162 h23 = __floats2bfloat162_rn(o2, o3);
        __nv_bfloat162 l23 = __floats2bfloat162_rn(o2 - __bfloat162float(h23.x),
                                                   o3 - __bfloat162float(h23.y));
        *(__nv_bfloat162*)(g_att_hi + i0) = h01;
        *(__nv_bfloat162*)(g_att_lo + i0) = l01;
        *(__nv_bfloat162*)(g_att_hi + i1) = h23;
        *(__nv_bfloat162*)(g_att_lo + i1) = l23;
    }
}

// ---------------------------------------------------------------------------
extern "C" void kernel_launch(void* const* d_in, const int* in_sizes, int n_in,
                              void* d_out, int out_size)
{
    const float* x      = (const float*)d_in[0];
    const float* w_qkv  = (const float*)d_in[1];
    const float* w_proj = (const float*)d_in[2];
    const float* b_proj = (const float*)d_in[3];
    float* out = (float*)d_out;

    cudaFuncSetAttribute(gemm_split_kernel,
                         cudaFuncAttributeMaxDynamicSharedMemorySize, GEMM_SMEM);
    cudaFuncSetAttribute(attn_mma_kernel,
                         cudaFuncAttributeMaxDynamicSharedMemorySize, ATTN_SMEM);

    __nv_bfloat16 *xhi, *xlo, *wqhi, *wqlo, *wphi, *wplo, *athi, *atlo;
    cudaGetSymbolAddress((void**)&xhi,  g_x_hi);
    cudaGetSymbolAddress((void**)&xlo,  g_x_lo);
    cudaGetSymbolAddress((void**)&wqhi, g_wq_hi);
    cudaGetSymbolAddress((void**)&wqlo, g_wq_lo);
    cudaGetSymbolAddress((void**)&wphi, g_wp_hi);
    cudaGetSymbolAddress((void**)&wplo, g_wp_lo);
    cudaGetSymbolAddress((void**)&athi, g_att_hi);
    cudaGetSymbolAddress((void**)&atlo, g_att_lo);

    // fp32 -> bf16 hi/lo splits
    split_kernel<<<(Tn*En/4 + 255)/256, 256>>>((const float4*)x,
        (__nv_bfloat162*)xhi, (__nv_bfloat162*)xlo, Tn*En/4);
    split_kernel<<<(F1n*En/4 + 255)/256, 256>>>((const float4*)w_qkv,
        (__nv_bfloat162*)wqhi, (__nv_bfloat162*)wqlo, F1n*En/4);
    split_kernel<<<(En*En/4 + 255)/256, 256>>>((const float4*)w_proj,
        (__nv_bfloat162*)wphi, (__nv_bfloat162*)wplo, En*En/4);

    // QKV GEMM (split-bf16 HMMA) -> bf16 hi/lo Q/K/V (Q pre-scaled)
    gemm_split_kernel<<<dim3(F1n/BNn, Tn/BMm), 256, GEMM_SMEM>>>(
        xhi, xlo, wqhi, wqlo, nullptr, nullptr, 0);

    // causal flash attention (split-bf16 HMMA)
    attn_mma_kernel<<<dim3(Sn/128, Bn*Hn), 256, ATTN_SMEM>>>();

    // output projection (split-bf16 HMMA) + bias
    gemm_split_kernel<<<dim3(En/BNn, Tn/BMm), 256, GEMM_SMEM>>>(
        athi, atlo, wphi, wplo, out, b_proj, 1);
}

// round 8
// speedup vs baseline: 2.8976x; 1.0060x over previous
#include <cuda_runtime.h>
#include <cuda_bf16.h>
#include <math.h>
#include <stdint.h>

#define Bn 4
#define Sn 2048
#define En 1024
#define Hn 16
#define HDn 64
#define Tn (Bn*Sn)        // 8192 tokens
#define F1n (3*En)        // 3072

#define QSCALE 0.180336880436f   // 0.125 * log2(e): scores land in exp2 domain

// ---------------------------------------------------------------------------
// Scratch (static device globals — allocation-free per harness rules)
// ---------------------------------------------------------------------------
__device__ __nv_bfloat16 g_qh[(size_t)Bn*Hn*Sn*HDn];  // [b*H+h][s][d] (scaled)
__device__ __nv_bfloat16 g_ql[(size_t)Bn*Hn*Sn*HDn];
__device__ __nv_bfloat16 g_kh[(size_t)Bn*Hn*Sn*HDn];
__device__ __nv_bfloat16 g_kl[(size_t)Bn*Hn*Sn*HDn];
__device__ __nv_bfloat16 g_vh[(size_t)Bn*Hn*Sn*HDn];
__device__ __nv_bfloat16 g_vl[(size_t)Bn*Hn*Sn*HDn];
__device__ __nv_bfloat16 g_x_hi[(size_t)Tn*En];
__device__ __nv_bfloat16 g_x_lo[(size_t)Tn*En];
__device__ __nv_bfloat16 g_wq_hi[(size_t)F1n*En];
__device__ __nv_bfloat16 g_wq_lo[(size_t)F1n*En];
__device__ __nv_bfloat16 g_wp_hi[(size_t)En*En];
__device__ __nv_bfloat16 g_wp_lo[(size_t)En*En];
__device__ __nv_bfloat16 g_att_hi[(size_t)Tn*En];
__device__ __nv_bfloat16 g_att_lo[(size_t)Tn*En];

// ---------------------------------------------------------------------------
// Helpers (baseline PTX only — no 'a'-suffix arch features)
// ---------------------------------------------------------------------------
__device__ __forceinline__ uint32_t smem_u32(const void* p) {
    uint32_t a;
    asm("{ .reg .u64 t; cvta.to.shared.u64 t, %1; cvt.u32.u64 %0, t; }" : "=r"(a) : "l"(p));
    return a;
}

__device__ __forceinline__ void ldgsts16(uint32_t dst, const void* src) {
    asm volatile("cp.async.cg.shared.global [%0], [%1], 16;" :: "r"(dst), "l"(src));
}

#define LDSM_X4(r0, r1, r2, r3, addr) \
    asm volatile("ldmatrix.sync.aligned.m8n8.x4.shared.b16 {%0,%1,%2,%3}, [%4];" \
        : "=r"(r0), "=r"(r1), "=r"(r2), "=r"(r3) : "r"(addr))

#define LDSM_X4_T(r0, r1, r2, r3, addr) \
    asm volatile("ldmatrix.sync.aligned.m8n8.x4.trans.shared.b16 {%0,%1,%2,%3}, [%4];" \
        : "=r"(r0), "=r"(r1), "=r"(r2), "=r"(r3) : "r"(addr))

__device__ __forceinline__ void mma16816(float c[4], const uint32_t a[4],
                                         uint32_t b0, uint32_t b1) {
    asm volatile(
        "mma.sync.aligned.m16n8k16.row.col.f32.bf16.bf16.f32 "
        "{%0,%1,%2,%3}, {%4,%5,%6,%7}, {%8,%9}, {%0,%1,%2,%3};"
        : "+f"(c[0]), "+f"(c[1]), "+f"(c[2]), "+f"(c[3])
        : "r"(a[0]), "r"(a[1]), "r"(a[2]), "r"(a[3]), "r"(b0), "r"(b1));
}

__device__ __forceinline__ float ex2f(float x) {
    float r; asm("ex2.approx.ftz.f32 %0, %1;" : "=f"(r) : "f"(x)); return r;
}

__device__ __forceinline__ uint32_t pack_bf2(float a, float b) {
    __nv_bfloat162 h = __floats2bfloat162_rn(a, b);
    return *reinterpret_cast<uint32_t*>(&h);
}

// GEMM smem swizzle: 64B rows, chunk XOR — 16B aligned, ldmatrix conflict-free
__device__ __forceinline__ uint32_t gsw(uint32_t row, uint32_t coloff) {
    return row*64u + (coloff ^ (((row >> 1) & 3u) << 4));
}

// ---------------------------------------------------------------------------
// Kernel 0: fp32 -> (bf16 hi, bf16 lo) split, float4-vectorized
// ---------------------------------------------------------------------------
__global__ __launch_bounds__(256) void split_kernel(
    const float4* __restrict__ src, __nv_bfloat162* __restrict__ hi,
    __nv_bfloat162* __restrict__ lo, int n4)
{
    int i = blockIdx.x * 256 + threadIdx.x;
    if (i >= n4) return;
    float4 v = src[i];
    __nv_bfloat16 h0 = __float2bfloat16(v.x), h1 = __float2bfloat16(v.y);
    __nv_bfloat16 h2 = __float2bfloat16(v.z), h3 = __float2bfloat16(v.w);
    __nv_bfloat162 a; a.x = h0; a.y = h1;
    __nv_bfloat162 b; b.x = h2; b.y = h3;
    __nv_bfloat162 c; c.x = __float2bfloat16(v.x - __bfloat162float(h0));
    c.y = __float2bfloat16(v.y - __bfloat162float(h1));
    __nv_bfloat162 d; d.x = __float2bfloat16(v.z - __bfloat162float(h2));
    d.y = __float2bfloat16(v.w - __bfloat162float(h3));
    hi[2*i] = a; hi[2*i+1] = b;
    lo[2*i] = c; lo[2*i+1] = d;
}

// ---------------------------------------------------------------------------
// Split-bf16 HMMA GEMM.  C[r][f] = sum_k A[r][k]*B[f][k]   (K = 1024)
// BM=128, BN=128, BK=32. 8 warps (2x4), each a 64x32 tile.
// 3-stage cp.async ring, ONE __syncthreads per iteration, 2 CTAs/SM.
// MMA issue order: split-term OUTER -> consecutive MMAs hit different
// accumulators (RAW distance 16 instead of 1).
//   mode 0: split C into bf16 hi/lo head-major q/k/v (q pre-scaled)
//   mode 1: C + bias -> out (fp32, row-major)
// ---------------------------------------------------------------------------
#define BMm 128
#define BNn 128
#define BKk 32
#define NKI (En/BKk)            // 32
#define OFF_ALO  8192           // 128*64
#define OFF_BHI 16384
#define OFF_BLO 24576
#define STAGEB  32768
#define GEMM_SMEM (3*STAGEB)    // 98304 (2 CTAs/SM = 196KB)

__global__ __launch_bounds__(256, 2) void gemm_split_kernel(
    const __nv_bfloat16* __restrict__ Ahi, const __nv_bfloat16* __restrict__ Alo,
    const __nv_bfloat16* __restrict__ Bhi, const __nv_bfloat16* __restrict__ Blo,
    float* __restrict__ outp, const float* __restrict__ bias, int mode)
{
    extern __shared__ char dsm[];
    const uint32_t sb = smem_u32(dsm);
    const int tid = threadIdx.x;
    const int wid = tid >> 5, lane = tid & 31;
    const int wy = wid & 1, wx = wid >> 1;         // warp tile: (wy*64, wx*32)
    const int t0 = blockIdx.y * BMm, f0 = blockIdx.x * BNn;

    #define LOAD_STAGE(ki, s) do {                                            \
        uint32_t base_ = sb + (uint32_t)(s)*STAGEB;                           \
        int kofs_ = (ki)*BKk;                                                 \
        _Pragma("unroll")                                                     \
        for (int jj = 0; jj < 2; jj++) {                                      \
            int c_ = tid + jj*256;                                            \
            uint32_t row_ = (uint32_t)(c_ >> 2), ch_ = (uint32_t)(c_ & 3);    \
            uint32_t so_ = gsw(row_, ch_*16u);                                \
            size_t ga_ = (size_t)(t0 + (int)row_)*En + kofs_ + (int)ch_*8;    \
            size_t gb_ = (size_t)(f0 + (int)row_)*En + kofs_ + (int)ch_*8;    \
            ldgsts16(base_ + so_,           Ahi + ga_);                       \
            ldgsts16(base_ + OFF_ALO + so_, Alo + ga_);                       \
            ldgsts16(base_ + OFF_BHI + so_, Bhi + gb_);                       \
            ldgsts16(base_ + OFF_BLO + so_, Blo + gb_);                       \
        }                                                                     \
    } while (0)

    float acc[4][4][4] = {};   // [mi][nj][frag]

    LOAD_STAGE(0, 0);
    asm volatile("cp.async.commit_group;");
    LOAD_STAGE(1, 1);
    asm volatile("cp.async.commit_group;");

    int slot = 0;
    for (int i = 0; i < NKI; i++) {
        asm volatile("cp.async.wait_group 1;");   // stage i resident
        __syncthreads();                          // also fences slot reuse

        if (i + 2 < NKI) {
            int ls = slot + 2; if (ls >= 3) ls -= 3;
            LOAD_STAGE(i + 2, ls);
        }
        asm volatile("cp.async.commit_group;");

        const uint32_t base = sb + (uint32_t)slot*STAGEB;
        const uint32_t lrow = lane & 15;
        const uint32_t lcol = (lane >> 4) << 4;

        #pragma unroll
        for (int kk = 0; kk < 2; kk++) {
            const uint32_t coff = (uint32_t)kk*32 + lcol;
            uint32_t ah[4][4], al[4][4];
            #pragma unroll
            for (int mi = 0; mi < 4; mi++) {
                uint32_t r = (uint32_t)(wy*64 + mi*16) + lrow;
                uint32_t addr = base + gsw(r, coff);
                LDSM_X4(ah[mi][0], ah[mi][1], ah[mi][2], ah[mi][3], addr);
                LDSM_X4(al[mi][0], al[mi][1], al[mi][2], al[mi][3], addr + OFF_ALO);
            }
            uint32_t bh[4][2], bl[4][2];
            #pragma unroll
            for (int pj = 0; pj < 2; pj++) {
                uint32_t r = (uint32_t)(wx*32 + pj*16) + lrow;
                uint32_t addr = base + OFF_BHI + gsw(r, coff);
                uint32_t r0, r1, r2, r3;
                LDSM_X4(r0, r1, r2, r3, addr);
                bh[2*pj][0] = r0; bh[2*pj+1][0] = r1;
                bh[2*pj][1] = r2; bh[2*pj+1][1] = r3;
                LDSM_X4(r0, r1, r2, r3, addr + (OFF_BLO - OFF_BHI));
                bl[2*pj][0] = r0; bl[2*pj+1][0] = r1;
                bl[2*pj][1] = r2; bl[2*pj+1][1] = r3;
            }
            // term-outer: consecutive MMAs target different accumulators
            #pragma unroll
            for (int mi = 0; mi < 4; mi++)
                #pragma unroll
                for (int nj = 0; nj < 4; nj++)
                    mma16816(acc[mi][nj], ah[mi], bh[nj][0], bh[nj][1]);
            #pragma unroll
            for (int mi = 0; mi < 4; mi++)
                #pragma unroll
                for (int nj = 0; nj < 4; nj++)
                    mma16816(acc[mi][nj], ah[mi], bl[nj][0], bl[nj][1]);
            #pragma unroll
            for (int mi = 0; mi < 4; mi++)
                #pragma unroll
                for (int nj = 0; nj < 4; nj++)
                    mma16816(acc[mi][nj], al[mi], bh[nj][0], bh[nj][1]);
        }
        if (++slot == 3) slot = 0;
    }

    // ---------------- epilogue ----------------------------------------------
    const int mrow = lane >> 2;
    const int ncol = (lane & 3) * 2;

    #pragma unroll
    for (int mi = 0; mi < 4; mi++) {
        #pragma unroll
        for (int half = 0; half < 2; half++) {
            int t = t0 + wy*64 + mi*16 + mrow + half*8;
            #pragma unroll
            for (int nj = 0; nj < 4; nj++) {
                int f = f0 + wx*32 + nj*8 + ncol;
                float v0 = acc[mi][nj][half*2 + 0];
                float v1 = acc[mi][nj][half*2 + 1];
                if (mode == 0) {
                    int bidx = t >> 11, sidx = t & 2047;
                    int hh = f / 192;
                    int c = f - hh*192;
                    int kind = c >> 6, d = c & 63;
                    if (kind == 0) { v0 *= QSCALE; v1 *= QSCALE; }
                    __nv_bfloat16* hp = (kind == 0) ? g_qh : ((kind == 1) ? g_kh : g_vh);
                    __nv_bfloat16* lp = (kind == 0) ? g_ql : ((kind == 1) ? g_kl : g_vl);
                    size_t idx = (((size_t)(bidx*Hn + hh))*Sn + sidx)*HDn + d;
                    __nv_bfloat162 h2 = __floats2bfloat162_rn(v0, v1);
                    __nv_bfloat162 l2 = __floats2bfloat162_rn(
                        v0 - __bfloat162float(h2.x), v1 - __bfloat162float(h2.y));
                    *(__nv_bfloat162*)(hp + idx) = h2;
                    *(__nv_bfloat162*)(lp + idx) = l2;
                } else {
                    float2* p = (float2*)&outp[(size_t)t*En + f];
                    *p = make_float2(v0 + bias[f], v1 + bias[f + 1]);
                }
            }
        }
    }
}

// ---------------------------------------------------------------------------
// Kernel 2: causal flash attention, split-bf16 HMMA, FA2 register layout.
// Block: 128 q-rows (8 warps x m16), kv tiles of 64, 3-stage cp.async ring,
// ONE __syncthreads per kv-tile. qt remapped longest-first.
// MMA issue order: split-term OUTER (RAW distance 8).
// ---------------------------------------------------------------------------
#define AROWB 144               // 64 bf16 = 128B data + 16B pad (16B-aligned)
#define A_QH 0
#define A_QL (128*AROWB)        // 18432
#define A_ST0 (2*128*AROWB)     // 36864
#define A_KH 0
#define A_KL (64*AROWB)         // 9216
#define A_VH (2*64*AROWB)       // 18432
#define A_VL (3*64*AROWB)       // 27648
#define A_STAGE (4*64*AROWB)    // 36864
#define ATTN_SMEM (A_ST0 + 3*A_STAGE)   // 147456

__global__ __launch_bounds__(256) void attn_mma_kernel()
{
    extern __shared__ char dsm[];
    const uint32_t sb = smem_u32(dsm);
    const int tid = threadIdx.x;
    const int wid = tid >> 5, lane = tid & 31;
    const int qt = gridDim.x - 1 - blockIdx.x;     // longest-first scheduling
    const int bh = blockIdx.y;
    const int q0 = qt * 128;
    const size_t gbase = (size_t)bh * Sn * HDn;
    const int nk = 2*qt + 2;                       // nk >= 2 always

    #define LOAD_KV(kt_, s_) do {                                             \
        uint32_t st_ = sb + A_ST0 + (uint32_t)(s_)*A_STAGE;                   \
        int kv_ = (kt_)*64;                                                   \
        _Pragma("unroll")                                                     \
        for (int j_ = 0; j_ < 2; j_++) {                                      \
            int c_ = tid + j_*256;                                            \
            int row_ = c_ >> 3, ch_ = c_ & 7;                                 \
            uint32_t so_ = (uint32_t)(row_*AROWB + ch_*16);                   \
            size_t go_ = gbase + (size_t)(kv_ + row_)*HDn + ch_*8;            \
            ldgsts16(st_ + A_KH + so_, g_kh + go_);                           \
            ldgsts16(st_ + A_KL + so_, g_kl + go_);                           \
            ldgsts16(st_ + A_VH + so_, g_vh + go_);                           \
            ldgsts16(st_ + A_VL + so_, g_vl + go_);                           \
        } } while (0)

    // Q tile (hi/lo) -> smem
    #pragma unroll
    for (int j = 0; j < 4; j++) {
        int c = tid + j*256;
        int row = c >> 3, ch = c & 7;
        uint32_t so = (uint32_t)(row*AROWB + ch*16);
        size_t go = gbase + (size_t)(q0 + row)*HDn + ch*8;
        ldgsts16(sb + A_QH + so, g_qh + go);
        ldgsts16(sb + A_QL + so, g_ql + go);
    }
    asm volatile("cp.async.commit_group;");
    LOAD_KV(0, 0);
    asm volatile("cp.async.commit_group;");
    LOAD_KV(1, 1);
    asm volatile("cp.async.commit_group;");

    asm volatile("cp.async.wait_group 2;");   // Q resident
    __syncthreads();

    // Q fragments (persist in registers)
    uint32_t qh_[4][4], ql_[4][4];
    {
        uint32_t r_ = (uint32_t)(wid*16 + (lane & 15));
        uint32_t cb = (uint32_t)((lane >> 4) << 4);
        #pragma unroll
        for (int kk = 0; kk < 4; kk++) {
            uint32_t addr = sb + A_QH + r_*AROWB + (uint32_t)kk*32 + cb;
            LDSM_X4(qh_[kk][0], qh_[kk][1], qh_[kk][2], qh_[kk][3], addr);
            LDSM_X4(ql_[kk][0], ql_[kk][1], ql_[kk][2], ql_[kk][3], addr + (A_QL - A_QH));
        }
    }

    float m0 = -INFINITY, m1 = -INFINITY, l0 = 0.f, l1 = 0.f;
    float acc[8][4] = {};

    int slot = 0;
    for (int kt = 0; kt < nk; kt++) {
        asm volatile("cp.async.wait_group 1;");   // KV_kt resident
        __syncthreads();                          // fences slot reuse

        if (kt + 2 < nk) {
            int ls = slot + 2; if (ls >= 3) ls -= 3;
            LOAD_KV(kt + 2, ls);
        }
        asm volatile("cp.async.commit_group;");

        const uint32_t st = sb + A_ST0 + (uint32_t)slot*A_STAGE;
        const int kv0 = kt * 64;

        // ---- S = Q @ K^T (3-term split, term-outer) ----
        float s[8][4] = {};
        {
            uint32_t r_ = (uint32_t)(lane & 15);
            uint32_t cb = (uint32_t)((lane >> 4) << 4);
            #pragma unroll
            for (int kk = 0; kk < 4; kk++) {
                uint32_t kh[8][2], kl[8][2];
                #pragma unroll
                for (int pj = 0; pj < 4; pj++) {
                    uint32_t addr = st + A_KH + (uint32_t)(pj*16 + r_)*AROWB
                                  + (uint32_t)kk*32 + cb;
                    uint32_t r0, r1, r2, r3;
                    LDSM_X4(r0, r1, r2, r3, addr);
                    kh[2*pj][0]=r0; kh[2*pj][1]=r2; kh[2*pj+1][0]=r1; kh[2*pj+1][1]=r3;
                    LDSM_X4(r0, r1, r2, r3, addr + (A_KL - A_KH));
                    kl[2*pj][0]=r0; kl[2*pj][1]=r2; kl[2*pj+1][0]=r1; kl[2*pj+1][1]=r3;
                }
                #pragma unroll
                for (int nj = 0; nj < 8; nj++)
                    mma16816(s[nj], qh_[kk], kh[nj][0], kh[nj][1]);
                #pragma unroll
                for (int nj = 0; nj < 8; nj++)
                    mma16816(s[nj], qh_[kk], kl[nj][0], kl[nj][1]);
                #pragma unroll
                for (int nj = 0; nj < 8; nj++)
                    mma16816(s[nj], ql_[kk], kh[nj][0], kh[nj][1]);
            }
        }

        // ---- causal mask ----
        const int rbase = q0 + wid*16 + (lane >> 2);
        if (kv0 + 63 > q0 + wid*16) {
            #pragma unroll
            for (int nj = 0; nj < 8; nj++)
                #pragma unroll
                for (int i = 0; i < 4; i++) {
                    int col = kv0 + nj*8 + (lane & 3)*2 + (i & 1);
                    int row = rbase + (i >> 1)*8;
                    if (col > row) s[nj][i] = -INFINITY;
                }
        }

        // ---- online softmax (exp2 domain) ----
        float mx0 = -INFINITY, mx1 = -INFINITY;
        #pragma unroll
        for (int nj = 0; nj < 8; nj++) {
            mx0 = fmaxf(mx0, fmaxf(s[nj][0], s[nj][1]));
            mx1 = fmaxf(mx1, fmaxf(s[nj][2], s[nj][3]));
        }
        mx0 = fmaxf(mx0, __shfl_xor_sync(0xffffffffu, mx0, 1));
        mx0 = fmaxf(mx0, __shfl_xor_sync(0xffffffffu, mx0, 2));
        mx1 = fmaxf(mx1, __shfl_xor_sync(0xffffffffu, mx1, 1));
        mx1 = fmaxf(mx1, __shfl_xor_sync(0xffffffffu, mx1, 2));
        float mn0 = fmaxf(m0, mx0), mn1 = fmaxf(m1, mx1);
        float al0 = ex2f(m0 - mn0), al1 = ex2f(m1 - mn1);
        m0 = mn0; m1 = mn1;
        float rs0 = 0.f, rs1 = 0.f;
        #pragma unroll
        for (int nj = 0; nj < 8; nj++) {
            float p0 = ex2f(s[nj][0] - mn0), p1 = ex2f(s[nj][1] - mn0);
            float p2 = ex2f(s[nj][2] - mn1), p3 = ex2f(s[nj][3] - mn1);
            s[nj][0] = p0; s[nj][1] = p1; s[nj][2] = p2; s[nj][3] = p3;
            rs0 += p0 + p1; rs1 += p2 + p3;
        }
        rs0 += __shfl_xor_sync(0xffffffffu, rs0, 1);
        rs0 += __shfl_xor_sync(0xffffffffu, rs0, 2);
        rs1 += __shfl_xor_sync(0xffffffffu, rs1, 1);
        rs1 += __shfl_xor_sync(0xffffffffu, rs1, 2);
        l0 = l0*al0 + rs0;
        l1 = l1*al1 + rs1;
        #pragma unroll
        for (int nj = 0; nj < 8; nj++) {
            acc[nj][0] *= al0; acc[nj][1] *= al0;
            acc[nj][2] *= al1; acc[nj][3] *= al1;
        }

        // ---- O += P @ V (3-term split, term-outer; V via ldmatrix.trans) ----
        {
            uint32_t rr = (uint32_t)(((lane >> 4) << 3) + (lane & 7));
            uint32_t cb = (uint32_t)(((lane >> 3) & 1) << 4);
            #pragma unroll
            for (int kk2 = 0; kk2 < 4; kk2++) {
                uint32_t pah[4], pal[4];
                #pragma unroll
                for (int tp = 0; tp < 2; tp++) {
                    int t_ = 2*kk2 + tp;
                    float p0 = s[t_][0], p1 = s[t_][1], p2 = s[t_][2], p3 = s[t_][3];
                    __nv_bfloat162 h01 = __floats2bfloat162_rn(p0, p1);
                    __nv_bfloat162 h23 = __floats2bfloat162_rn(p2, p3);
                    pah[2*tp+0] = *reinterpret_cast<uint32_t*>(&h01);
                    pah[2*tp+1] = *reinterpret_cast<uint32_t*>(&h23);
                    pal[2*tp+0] = pack_bf2(p0 - __bfloat162float(h01.x),
                                           p1 - __bfloat162float(h01.y));
                    pal[2*tp+1] = pack_bf2(p2 - __bfloat162float(h23.x),
                                           p3 - __bfloat162float(h23.y));
                }
                uint32_t bvh[8][2], bvl[8][2];
                #pragma unroll
                for (int dj = 0; dj < 4; dj++) {
                    uint32_t addr = st + A_VH + (uint32_t)(kk2*16 + rr)*AROWB
                                  + (uint32_t)dj*32 + cb;
                    uint32_t r0, r1, r2, r3;
                    LDSM_X4_T(r0, r1, r2, r3, addr);
                    bvh[2*dj][0]=r0; bvh[2*dj][1]=r2; bvh[2*dj+1][0]=r1; bvh[2*dj+1][1]=r3;
                    LDSM_X4_T(r0, r1, r2, r3, addr + (A_VL - A_VH));
                    bvl[2*dj][0]=r0; bvl[2*dj][1]=r2; bvl[2*dj+1][0]=r1; bvl[2*dj+1][1]=r3;
                }
                #pragma unroll
                for (int nj = 0; nj < 8; nj++)
                    mma16816(acc[nj], pah, bvh[nj][0], bvh[nj][1]);
                #pragma unroll
                for (int nj = 0; nj < 8; nj++)
                    mma16816(acc[nj], pah, bvl[nj][0], bvl[nj][1]);
                #pragma unroll
                for (int nj = 0; nj < 8; nj++)
                    mma16816(acc[nj], pal, bvh[nj][0], bvh[nj][1]);
            }
        }

        if (++slot == 3) slot = 0;
    }

    // ---- epilogue: normalize, write bf16 hi/lo for proj GEMM ----
    float inv0 = 1.f / l0, inv1 = 1.f / l1;
    const int b = bh >> 4, h = bh & 15;
    const int r0_ = q0 + wid*16 + (lane >> 2);
    #pragma unroll
    for (int nj = 0; nj < 8; nj++) {
        int d = nj*8 + (lane & 3)*2;
        size_t i0 = (size_t)(b*Sn + r0_)*En + h*HDn + d;
        size_t i1 = i0 + (size_t)8*En;
        float o0 = acc[nj][0]*inv0, o1 = acc[nj][1]*inv0;
        float o2 = acc[nj][2]*inv1, o3 = acc[nj][3]*inv1;
        __nv_bfloat162 h01 = __floats2bfloat162_rn(o0, o1);
        __nv_bfloat162 l01 = __floats2bfloat162_rn(o0 - __bfloat162float(h01.x),
                                                   o1 - __bfloat162float(h01.y));
        __nv_bfloat162 h23 = __floats2bfloat162_rn(o2, o3);
        __nv_bfloat162 l23 = __floats2bfloat162_rn(o2 - __bfloat162float(h23.x),
                                                   o3 - __bfloat162float(h23.y));
        *(__nv_bfloat162*)(g_att_hi + i0) = h01;
        *(__nv_bfloat162*)(g_att_lo + i0) = l01;
        *(__nv_bfloat162*)(g_att_hi + i1) = h23;
        *(__nv_bfloat162*)(g_att_lo + i1) = l23;
    }
}

// ---------------------------------------------------------------------------
extern "C" void kernel_launch(void* const* d_in, const int* in_sizes, int n_in,
                              void* d_out, int out_size)
{
    const float* x      = (const float*)d_in[0];
    const float* w_qkv  = (const float*)d_in[1];
    const float* w_proj = (const float*)d_in[2];
    const float* b_proj = (const float*)d_in[3];
    float* out = (float*)d_out;

    cudaFuncSetAttribute(gemm_split_kernel,
                         cudaFuncAttributeMaxDynamicSharedMemorySize, GEMM_SMEM);
    cudaFuncSetAttribute(attn_mma_kernel,
                         cudaFuncAttributeMaxDynamicSharedMemorySize, ATTN_SMEM);

    __nv_bfloat16 *xhi, *xlo, *wqhi, *wqlo, *wphi, *wplo, *athi, *atlo;
    cudaGetSymbolAddress((void**)&xhi,  g_x_hi);
    cudaGetSymbolAddress((void**)&xlo,  g_x_lo);
    cudaGetSymbolAddress((void**)&wqhi, g_wq_hi);
    cudaGetSymbolAddress((void**)&wqlo, g_wq_lo);
    cudaGetSymbolAddress((void**)&wphi, g_wp_hi);
    cudaGetSymbolAddress((void**)&wplo, g_wp_lo);
    cudaGetSymbolAddress((void**)&athi, g_att_hi);
    cudaGetSymbolAddress((void**)&atlo, g_att_lo);

    // fp32 -> bf16 hi/lo splits
    split_kernel<<<(Tn*En/4 + 255)/256, 256>>>((const float4*)x,
        (__nv_bfloat162*)xhi, (__nv_bfloat162*)xlo, Tn*En/4);
    split_kernel<<<(F1n*En/4 + 255)/256, 256>>>((const float4*)w_qkv,
        (__nv_bfloat162*)wqhi, (__nv_bfloat162*)wqlo, F1n*En/4);
    split_kernel<<<(En*En/4 + 255)/256, 256>>>((const float4*)w_proj,
        (__nv_bfloat162*)wphi, (__nv_bfloat162*)wplo, En*En/4);

    // QKV GEMM (split-bf16 HMMA) -> bf16 hi/lo Q/K/V (Q pre-scaled)
    gemm_split_kernel<<<dim3(F1n/BNn, Tn/BMm), 256, GEMM_SMEM>>>(
        xhi, xlo, wqhi, wqlo, nullptr, nullptr, 0);

    // causal flash attention (split-bf16 HMMA)
    attn_mma_kernel<<<dim3(Sn/128, Bn*Hn), 256, ATTN_SMEM>>>();

    // output projection (split-bf16 HMMA) + bias
    gemm_split_kernel<<<dim3(En/BNn, Tn/BMm), 256, GEMM_SMEM>>>(
        athi, atlo, wphi, wplo, out, b_proj, 1);
}